// round 8
// baseline (speedup 1.0000x reference)
#include <cuda_runtime.h>
#include <cuda_bf16.h>
#include <cuda_fp16.h>
#include <cstdint>

// Problem constants
#define B 2
#define S 2048
#define E 2048
#define HQ 32
#define HK 8
#define D 64

// ---------------------------------------------------------------------------
// Scratch (device globals)
// ---------------------------------------------------------------------------
__device__ float g_qkv[(size_t)B * S * 3072];            // fused QKV fp32

__device__ __nv_bfloat16 g_xhi[(size_t)B * S * E];
__device__ __nv_bfloat16 g_xlo[(size_t)B * S * E];
__device__ __nv_bfloat16 g_wqkvhi[(size_t)3072 * E];     // [N=3072, K=2048]
__device__ __nv_bfloat16 g_wqkvlo[(size_t)3072 * E];
__device__ __half        g_wohf[(size_t)E * HQ * D];     // Wo^T fp16 (single)

// int8 2-term quantized q/k (post-RoPE) + per-head-row scales
__device__ int8_t g_q0[(size_t)B * S * HQ * D];
__device__ int8_t g_q1[(size_t)B * S * HQ * D];
__device__ int8_t g_k0[(size_t)B * S * HK * D];
__device__ int8_t g_k1[(size_t)B * S * HK * D];
__device__ float  g_sq[(size_t)B * HQ * S];              // head-major
__device__ float  g_sk[(size_t)B * HK * S];              // head-major
__device__ __half g_vh[(size_t)B * S * HK * D];          // v fp16 (single)
__device__ __half g_of[(size_t)B * S * HQ * D];          // attention out, fp16

// ---------------------------------------------------------------------------
// PTX helpers (base-target safe)
// ---------------------------------------------------------------------------
__device__ __forceinline__ uint32_t smem_u32(const void* p) {
    uint32_t a;
    asm("{ .reg .u64 t; cvta.to.shared.u64 t, %1; cvt.u32.u64 %0, t; }"
        : "=r"(a) : "l"(p));
    return a;
}
__device__ __forceinline__ void cp16(uint32_t dst, const void* src) {
    asm volatile("cp.async.cg.shared.global [%0], [%1], 16;"
                 :: "r"(dst), "l"(src) : "memory");
}
__device__ __forceinline__ void cp_commit() {
    asm volatile("cp.async.commit_group;" ::: "memory");
}
template <int N>
__device__ __forceinline__ void cp_wait() {
    asm volatile("cp.async.wait_group %0;" :: "n"(N) : "memory");
}
__device__ __forceinline__ void ldm4(uint32_t* r, uint32_t addr) {
    asm volatile("ldmatrix.sync.aligned.m8n8.x4.shared.b16 {%0,%1,%2,%3}, [%4];"
                 : "=r"(r[0]), "=r"(r[1]), "=r"(r[2]), "=r"(r[3]) : "r"(addr));
}
__device__ __forceinline__ void ldm4t(uint32_t* r, uint32_t addr) {
    asm volatile("ldmatrix.sync.aligned.m8n8.x4.trans.shared.b16 {%0,%1,%2,%3}, [%4];"
                 : "=r"(r[0]), "=r"(r[1]), "=r"(r[2]), "=r"(r[3]) : "r"(addr));
}
__device__ __forceinline__ void mma_bf16(float* c, const uint32_t* a,
                                         const uint32_t* b) {
    asm volatile(
        "mma.sync.aligned.m16n8k16.row.col.f32.bf16.bf16.f32 "
        "{%0,%1,%2,%3}, {%4,%5,%6,%7}, {%8,%9}, {%0,%1,%2,%3};"
        : "+f"(c[0]), "+f"(c[1]), "+f"(c[2]), "+f"(c[3])
        : "r"(a[0]), "r"(a[1]), "r"(a[2]), "r"(a[3]), "r"(b[0]), "r"(b[1]));
}
__device__ __forceinline__ void mma_f16(float* c, const uint32_t* a,
                                        const uint32_t* b) {
    asm volatile(
        "mma.sync.aligned.m16n8k16.row.col.f32.f16.f16.f32 "
        "{%0,%1,%2,%3}, {%4,%5,%6,%7}, {%8,%9}, {%0,%1,%2,%3};"
        : "+f"(c[0]), "+f"(c[1]), "+f"(c[2]), "+f"(c[3])
        : "r"(a[0]), "r"(a[1]), "r"(a[2]), "r"(a[3]), "r"(b[0]), "r"(b[1]));
}
__device__ __forceinline__ void mma_s8(int* c, const uint32_t* a,
                                       const uint32_t* b) {
    asm volatile(
        "mma.sync.aligned.m16n8k32.row.col.s32.s8.s8.s32 "
        "{%0,%1,%2,%3}, {%4,%5,%6,%7}, {%8,%9}, {%0,%1,%2,%3};"
        : "+r"(c[0]), "+r"(c[1]), "+r"(c[2]), "+r"(c[3])
        : "r"(a[0]), "r"(a[1]), "r"(a[2]), "r"(a[3]), "r"(b[0]), "r"(b[1]));
}
__device__ __forceinline__ uint32_t packbf(__nv_bfloat16 a, __nv_bfloat16 b) {
    __nv_bfloat162 t = __halves2bfloat162(a, b);
    return *(uint32_t*)&t;
}
__device__ __forceinline__ uint32_t packh(float x, float y) {
    __half2 t = __floats2half2_rn(x, y);
    return *(uint32_t*)&t;
}
__device__ __forceinline__ void split2(float x, float y,
                                       uint32_t& hi, uint32_t& lo) {
    __nv_bfloat16 hx = __float2bfloat16(x), hy = __float2bfloat16(y);
    __nv_bfloat16 lx = __float2bfloat16(x - __bfloat162float(hx));
    __nv_bfloat16 ly = __float2bfloat16(y - __bfloat162float(hy));
    hi = packbf(hx, hy);
    lo = packbf(lx, ly);
}

// ---------------------------------------------------------------------------
// Split fp32 -> bf16 hi/lo
// ---------------------------------------------------------------------------
__global__ void split_kernel(const float* __restrict__ src,
                             __nv_bfloat16* __restrict__ hi,
                             __nv_bfloat16* __restrict__ lo, int n4)
{
    int i = blockIdx.x * blockDim.x + threadIdx.x;
    if (i >= n4) return;
    float4 v = ((const float4*)src)[i];
    uint32_t h0, l0, h1, l1;
    split2(v.x, v.y, h0, l0);
    split2(v.z, v.w, h1, l1);
    ((uint32_t*)hi)[2*i]   = h0;
    ((uint32_t*)hi)[2*i+1] = h1;
    ((uint32_t*)lo)[2*i]   = l0;
    ((uint32_t*)lo)[2*i+1] = l1;
}

// ---------------------------------------------------------------------------
// Transpose W[K,N] -> Wt[N,K], bf16 hi/lo
// ---------------------------------------------------------------------------
__global__ __launch_bounds__(256) void transpose_split_kernel(
    const float* __restrict__ W,
    __nv_bfloat16* __restrict__ hiT,
    __nv_bfloat16* __restrict__ loT, int K, int N)
{
    __shared__ float t[32][33];
    int n0 = blockIdx.x * 32, k0 = blockIdx.y * 32;
    int tx = threadIdx.x, ty = threadIdx.y;
#pragma unroll
    for (int r = 0; r < 4; r++)
        t[ty + r*8][tx] = W[(size_t)(k0 + ty + r*8) * N + n0 + tx];
    __syncthreads();
#pragma unroll
    for (int r = 0; r < 4; r++) {
        int n = n0 + ty + r*8;
        float v = t[tx][ty + r*8];
        __nv_bfloat16 h = __float2bfloat16(v);
        hiT[(size_t)n * K + k0 + tx] = h;
        loT[(size_t)n * K + k0 + tx] = __float2bfloat16(v - __bfloat162float(h));
    }
}

// Transpose W[K,N] -> Wt[N,K], single fp16
__global__ __launch_bounds__(256) void transpose_h_kernel(
    const float* __restrict__ W,
    __half* __restrict__ hT, int K, int N)
{
    __shared__ float t[32][33];
    int n0 = blockIdx.x * 32, k0 = blockIdx.y * 32;
    int tx = threadIdx.x, ty = threadIdx.y;
#pragma unroll
    for (int r = 0; r < 4; r++)
        t[ty + r*8][tx] = W[(size_t)(k0 + ty + r*8) * N + n0 + tx];
    __syncthreads();
#pragma unroll
    for (int r = 0; r < 4; r++) {
        int n = n0 + ty + r*8;
        hT[(size_t)n * K + k0 + tx] = __float2half_rn(t[tx][ty + r*8]);
    }
}

// ---------------------------------------------------------------------------
// mma.sync bf16 3-term GEMM (verified)
// ---------------------------------------------------------------------------
#define TSTRIDE 80
#define TILE_BYTES (128 * TSTRIDE)
#define STAGE_BYTES (4 * TILE_BYTES)
#define GEMM_SMEM (2 * STAGE_BYTES)

__device__ __forceinline__ void load_stage(
    uint32_t base, int tid,
    const __nv_bfloat16* Ah, const __nv_bfloat16* Al,
    const __nv_bfloat16* Bh, const __nv_bfloat16* Bl,
    int K, int k0)
{
    int ch = tid & 3;
    int rhalf = tid >> 2;
#pragma unroll
    for (int i = 0; i < 8; i++) {
        int tile = i >> 1;
        int row = (i & 1) * 64 + rhalf;
        uint32_t dst = base + tile * TILE_BYTES + row * TSTRIDE + ch * 16;
        const __nv_bfloat16* src =
            (tile == 0) ? Ah : (tile == 1) ? Al : (tile == 2) ? Bh : Bl;
        cp16(dst, src + (size_t)row * K + k0 + ch * 8);
    }
}

__global__ __launch_bounds__(256) void mma_gemm_kernel(
    int M, int N, int K,
    const __nv_bfloat16* __restrict__ Ahi, const __nv_bfloat16* __restrict__ Alo,
    const __nv_bfloat16* __restrict__ Bhi, const __nv_bfloat16* __restrict__ Blo,
    float* __restrict__ C)
{
    extern __shared__ char smem[];
    uint32_t sb = smem_u32(smem);
    int tid = threadIdx.x;
    int lane = tid & 31, wid = tid >> 5;
    int wm = wid & 1, wn = wid >> 1;
    int bm = blockIdx.y * 128, bn = blockIdx.x * 128;

    const __nv_bfloat16* Ah = Ahi + (size_t)bm * K;
    const __nv_bfloat16* Al = Alo + (size_t)bm * K;
    const __nv_bfloat16* Bh = Bhi + (size_t)bn * K;
    const __nv_bfloat16* Bl = Blo + (size_t)bn * K;

    float acc[4][4][4];
#pragma unroll
    for (int i = 0; i < 4; i++)
#pragma unroll
        for (int j = 0; j < 4; j++)
#pragma unroll
            for (int r = 0; r < 4; r++) acc[i][j][r] = 0.f;

    uint32_t aoff = (uint32_t)((wm * 64 + (lane & 15)) * TSTRIDE + (lane >> 4) * 16);
    uint32_t boff = (uint32_t)((wn * 32 + ((lane >> 4) * 8) + (lane & 7)) * TSTRIDE
                               + ((lane >> 3) & 1) * 16);

    const int nch = K >> 5;
    load_stage(sb, tid, Ah, Al, Bh, Bl, K, 0);
    cp_commit();

    for (int ch = 0; ch < nch; ch++) {
        if (ch + 1 < nch) {
            load_stage(sb + ((ch + 1) & 1) * STAGE_BYTES, tid,
                       Ah, Al, Bh, Bl, K, (ch + 1) << 5);
            cp_commit();
            cp_wait<1>();
        } else {
            cp_wait<0>();
        }
        __syncthreads();

        uint32_t st = sb + (ch & 1) * STAGE_BYTES;
        uint32_t sAhi = st;
        uint32_t sAlo = st + TILE_BYTES;
        uint32_t sBhi = st + 2 * TILE_BYTES;
        uint32_t sBlo = st + 3 * TILE_BYTES;

#pragma unroll
        for (int ks = 0; ks < 2; ks++) {
            uint32_t kb = ks * 32;
            uint32_t bh[8], bl[8], a[16];
            ldm4(bh + 0, sBhi + boff + kb);
            ldm4(bh + 4, sBhi + boff + 16 * TSTRIDE + kb);
            ldm4(bl + 0, sBlo + boff + kb);
            ldm4(bl + 4, sBlo + boff + 16 * TSTRIDE + kb);
#pragma unroll
            for (int mt = 0; mt < 4; mt++)
                ldm4(a + 4 * mt, sAhi + aoff + mt * 16 * TSTRIDE + kb);
#pragma unroll
            for (int mt = 0; mt < 4; mt++)
#pragma unroll
                for (int nt = 0; nt < 4; nt++)
                    mma_bf16(acc[mt][nt], a + 4 * mt, bh + 2 * nt);
#pragma unroll
            for (int mt = 0; mt < 4; mt++)
#pragma unroll
                for (int nt = 0; nt < 4; nt++)
                    mma_bf16(acc[mt][nt], a + 4 * mt, bl + 2 * nt);
#pragma unroll
            for (int mt = 0; mt < 4; mt++)
                ldm4(a + 4 * mt, sAlo + aoff + mt * 16 * TSTRIDE + kb);
#pragma unroll
            for (int mt = 0; mt < 4; mt++)
#pragma unroll
                for (int nt = 0; nt < 4; nt++)
                    mma_bf16(acc[mt][nt], a + 4 * mt, bh + 2 * nt);
        }
        __syncthreads();
    }

    int r0 = bm + wm * 64 + (lane >> 2);
    int c0 = bn + wn * 32 + (lane & 3) * 2;
#pragma unroll
    for (int mt = 0; mt < 4; mt++) {
#pragma unroll
        for (int nt = 0; nt < 4; nt++) {
            int row = r0 + mt * 16;
            int col = c0 + nt * 8;
            *(float2*)&C[(size_t)row * N + col] =
                make_float2(acc[mt][nt][0], acc[mt][nt][1]);
            *(float2*)&C[(size_t)(row + 8) * N + col] =
                make_float2(acc[mt][nt][2], acc[mt][nt][3]);
        }
    }
}

// ---------------------------------------------------------------------------
// fp16 single-term GEMM: C = A(fp16) * B^T(fp16).  2 staged tiles.
// ---------------------------------------------------------------------------
#define STAGE1_BYTES (2 * TILE_BYTES)
#define GEMM1_SMEM (2 * STAGE1_BYTES)

__device__ __forceinline__ void load_stage1(
    uint32_t base, int tid,
    const __half* A, const __half* Bh, int K, int k0)
{
    int ch = tid & 3;
    int rhalf = tid >> 2;
#pragma unroll
    for (int i = 0; i < 4; i++) {
        int tile = i >> 1;
        int row = (i & 1) * 64 + rhalf;
        uint32_t dst = base + tile * TILE_BYTES + row * TSTRIDE + ch * 16;
        const __half* src = (tile == 0) ? A : Bh;
        cp16(dst, src + (size_t)row * K + k0 + ch * 8);
    }
}

__global__ __launch_bounds__(256) void mma_gemm1_kernel(
    int M, int N, int K,
    const __half* __restrict__ A,
    const __half* __restrict__ Bhi,
    float* __restrict__ C)
{
    extern __shared__ char smem[];
    uint32_t sb = smem_u32(smem);
    int tid = threadIdx.x;
    int lane = tid & 31, wid = tid >> 5;
    int wm = wid & 1, wn = wid >> 1;
    int bm = blockIdx.y * 128, bn = blockIdx.x * 128;

    const __half* Ap = A + (size_t)bm * K;
    const __half* Bh = Bhi + (size_t)bn * K;

    float acc[4][4][4];
#pragma unroll
    for (int i = 0; i < 4; i++)
#pragma unroll
        for (int j = 0; j < 4; j++)
#pragma unroll
            for (int r = 0; r < 4; r++) acc[i][j][r] = 0.f;

    uint32_t aoff = (uint32_t)((wm * 64 + (lane & 15)) * TSTRIDE + (lane >> 4) * 16);
    uint32_t boff = (uint32_t)((wn * 32 + ((lane >> 4) * 8) + (lane & 7)) * TSTRIDE
                               + ((lane >> 3) & 1) * 16);

    const int nch = K >> 5;
    load_stage1(sb, tid, Ap, Bh, K, 0);
    cp_commit();

    for (int ch = 0; ch < nch; ch++) {
        if (ch + 1 < nch) {
            load_stage1(sb + ((ch + 1) & 1) * STAGE1_BYTES, tid,
                        Ap, Bh, K, (ch + 1) << 5);
            cp_commit();
            cp_wait<1>();
        } else {
            cp_wait<0>();
        }
        __syncthreads();

        uint32_t st = sb + (ch & 1) * STAGE1_BYTES;
        uint32_t sA = st;
        uint32_t sB = st + TILE_BYTES;

#pragma unroll
        for (int ks = 0; ks < 2; ks++) {
            uint32_t kb = ks * 32;
            uint32_t bh[8], a[16];
            ldm4(bh + 0, sB + boff + kb);
            ldm4(bh + 4, sB + boff + 16 * TSTRIDE + kb);
#pragma unroll
            for (int mt = 0; mt < 4; mt++)
                ldm4(a + 4 * mt, sA + aoff + mt * 16 * TSTRIDE + kb);
#pragma unroll
            for (int mt = 0; mt < 4; mt++)
#pragma unroll
                for (int nt = 0; nt < 4; nt++)
                    mma_f16(acc[mt][nt], a + 4 * mt, bh + 2 * nt);
        }
        __syncthreads();
    }

    int r0 = bm + wm * 64 + (lane >> 2);
    int c0 = bn + wn * 32 + (lane & 3) * 2;
#pragma unroll
    for (int mt = 0; mt < 4; mt++) {
#pragma unroll
        for (int nt = 0; nt < 4; nt++) {
            int row = r0 + mt * 16;
            int col = c0 + nt * 8;
            *(float2*)&C[(size_t)row * N + col] =
                make_float2(acc[mt][nt][0], acc[mt][nt][1]);
            *(float2*)&C[(size_t)(row + 8) * N + col] =
                make_float2(acc[mt][nt][2], acc[mt][nt][3]);
        }
    }
}

// ---------------------------------------------------------------------------
// Fused RoPE + quantize. One warp per head-row.
// q/k -> int8 2-term (x ≈ s·(a0 + a1/252)) + per-row scale; v -> fp16.
// heads 0-31: q, 32-39: k, 40-47: v.
// ---------------------------------------------------------------------------
__global__ __launch_bounds__(256) void rope_quant_kernel(
    const float* __restrict__ qkv,
    const float* __restrict__ cs,
    const float* __restrict__ sn)
{
    int gw = (blockIdx.x * 256 + threadIdx.x) >> 5;
    int lane = threadIdx.x & 31;
    int rowid = gw / 48;
    int head = gw - rowid * 48;
    int s = rowid & (S - 1);
    int b = rowid >> 11;

    const float* base;
    if (head < 32)      base = qkv + (size_t)rowid * 3072 + head * 64;
    else if (head < 40) base = qkv + (size_t)rowid * 3072 + 2048 + (head - 32) * 64;
    else                base = qkv + (size_t)rowid * 3072 + 2560 + (head - 40) * 64;
    float v1 = base[lane], v2 = base[lane + 32];

    if (head < 40) {
        float c = cs[s * 32 + lane], si = sn[s * 32 + lane];
        float r1 = v1 * c - v2 * si;
        float r2 = v2 * c + v1 * si;
        float mx = fmaxf(fabsf(r1), fabsf(r2));
#pragma unroll
        for (int o = 16; o; o >>= 1)
            mx = fmaxf(mx, __shfl_xor_sync(0xffffffffu, mx, o));
        float sc = mx * (1.f / 127.f);
        float inv = (mx > 0.f) ? 127.f / mx : 0.f;
        float t1 = r1 * inv, t2 = r2 * inv;
        int a1 = __float2int_rn(t1), a2 = __float2int_rn(t2);
        int c1 = __float2int_rn((t1 - (float)a1) * 252.f);
        int c2 = __float2int_rn((t2 - (float)a2) * 252.f);
        int8_t *d0, *d1;
        float* sdst;
        if (head < 32) {
            size_t o = ((size_t)rowid * HQ + head) * 64;
            d0 = g_q0 + o; d1 = g_q1 + o;
            sdst = g_sq + ((size_t)b * HQ + head) * S + s;
        } else {
            int h2 = head - 32;
            size_t o = ((size_t)rowid * HK + h2) * 64;
            d0 = g_k0 + o; d1 = g_k1 + o;
            sdst = g_sk + ((size_t)b * HK + h2) * S + s;
        }
        d0[lane] = (int8_t)a1; d0[lane + 32] = (int8_t)a2;
        d1[lane] = (int8_t)c1; d1[lane + 32] = (int8_t)c2;
        if (lane == 0) *sdst = sc;
    } else {
        int h2 = head - 40;
        size_t o = ((size_t)rowid * HK + h2) * 64;
        g_vh[o + lane] = __float2half_rn(v1);
        g_vh[o + lane + 32] = __float2half_rn(v2);
    }
}

// ---------------------------------------------------------------------------
// Tensor-core flash attention.
// QK: int8 2-term (s8 m16n8k32, groups hh + hl + lh). PV: fp16 single.
// ---------------------------------------------------------------------------
#define K8STRIDE 80
#define K8TILE (64 * K8STRIDE)          // 5120
#define V8OFF (2 * K8TILE)              // 10240
#define VTILE (64 * 144)                // 9216
#define SK8OFF (V8OFF + VTILE)          // 19456
#define FSTAGE8 (SK8OFF + 256)          // 19712
#define QT8 (128 * K8STRIDE)            // 10240
#define FLASH_SMEM (2 * FSTAGE8)        // 39424

__global__ __launch_bounds__(256) void flash_mma_kernel()
{
    extern __shared__ char smem[];
    uint32_t sb = smem_u32(smem);
    int tid = threadIdx.x;
    int lane = tid & 31, wq = tid >> 5;
    int qbase = blockIdx.x * 128;
    int h = blockIdx.y, b = blockIdx.z;
    int kh = h >> 2;

    // ---- stage Q int8 (q0, q1) and build fragments ----
#pragma unroll
    for (int i = 0; i < 4; i++) {
        int lin = i * 256 + tid;
        int arr = lin >> 9;
        int rem = lin & 511;
        int row = rem >> 2;
        int seg = rem & 3;
        const int8_t* src = (arr ? g_q1 : g_q0)
            + ((size_t)(b * S + qbase + row) * HQ + h) * 64 + seg * 16;
        cp16(sb + arr * QT8 + row * K8STRIDE + seg * 16, src);
    }
    cp_commit();
    cp_wait<0>();
    __syncthreads();

    uint32_t q0f[2][4], q1f[2][4];
    {
        uint32_t qoff = (uint32_t)((wq * 16 + (lane & 15)) * K8STRIDE + (lane >> 4) * 16);
#pragma unroll
        for (int sp = 0; sp < 2; sp++) {
            ldm4(q0f[sp], sb + qoff + sp * 32);
            ldm4(q1f[sp], sb + QT8 + qoff + sp * 32);
        }
    }
    float sq0 = g_sq[((size_t)b * HQ + h) * S + qbase + wq * 16 + (lane >> 2)];
    float sq1 = g_sq[((size_t)b * HQ + h) * S + qbase + wq * 16 + (lane >> 2) + 8];
    __syncthreads();

    // ---- kv staging ----
    const int8_t* k0src = g_k0 + ((size_t)b * S * HK + kh) * 64;
    const int8_t* k1src = g_k1 + ((size_t)b * S * HK + kh) * 64;
    const uint8_t* vsrc = (const uint8_t*)(g_vh + ((size_t)b * S * HK + kh) * D);
    const uint8_t* sksrc = (const uint8_t*)(g_sk + ((size_t)b * HK + kh) * S);

    auto prefetch = [&](int t) {
        uint32_t base = sb + (t & 1) * FSTAGE8;
        int key0 = t * 64;
        // k0/k1 tiles: 64 rows x 64B, stride 80
#pragma unroll
        for (int i = 0; i < 2; i++) {
            int lin = i * 256 + tid;
            int arr = lin >> 8;
            int rem = lin & 255;
            int row = rem >> 2;
            int seg = rem & 3;
            const int8_t* src = (arr ? k1src : k0src)
                + (size_t)(key0 + row) * (HK * 64) + seg * 16;
            cp16(base + arr * K8TILE + row * K8STRIDE + seg * 16, src);
        }
        // v tile: 64 rows x 128B, stride 144
#pragma unroll
        for (int i = 0; i < 2; i++) {
            int lin = i * 256 + tid;
            int row = lin >> 3;
            int seg = lin & 7;
            cp16(base + V8OFF + row * 144 + seg * 16,
                 vsrc + (size_t)(key0 + row) * (HK * D * 2) + seg * 16);
        }
        // sk: 64 floats
        if (tid < 16)
            cp16(base + SK8OFF + tid * 16, sksrc + (size_t)key0 * 4 + tid * 16);
        cp_commit();
    };

    uint32_t boff8 = (uint32_t)(((lane >> 4) * 8 + (lane & 7)) * K8STRIDE
                                + ((lane >> 3) & 1) * 16);
    uint32_t voff = (uint32_t)((lane & 15) * 144 + (lane >> 4) * 16);

    float o_[8][4];
#pragma unroll
    for (int nt = 0; nt < 8; nt++)
#pragma unroll
        for (int r = 0; r < 4; r++) o_[nt][r] = 0.f;
    float m0 = -1e30f, m1 = -1e30f, l0 = 0.f, l1 = 0.f;

    prefetch(0);

    const float INV252 = 1.f / 252.f;
    const int NT = S / 64;
    for (int t = 0; t < NT; t++) {
        if (t + 1 < NT) { prefetch(t + 1); cp_wait<1>(); }
        else           { cp_wait<0>(); }
        __syncthreads();

        uint32_t st = sb + (t & 1) * FSTAGE8;
        uint32_t sK0 = st, sK1 = st + K8TILE;
        uint32_t sVh = st + V8OFF;
        const float* skp = (const float*)(smem + (size_t)(t & 1) * FSTAGE8 + SK8OFF);

        // ---- QK int8: acc0 = q0k0, acc1 = q0k1 + q1k0 ----
        int acc0[8][4], acc1[8][4];
#pragma unroll
        for (int nt = 0; nt < 8; nt++)
#pragma unroll
            for (int r = 0; r < 4; r++) { acc0[nt][r] = 0; acc1[nt][r] = 0; }

#pragma unroll
        for (int sp = 0; sp < 2; sp++) {
            uint32_t b0[16], b1[16];
#pragma unroll
            for (int j = 0; j < 4; j++)
                ldm4(b0 + 4*j, sK0 + boff8 + j * 16 * K8STRIDE + sp * 32);
#pragma unroll
            for (int j = 0; j < 4; j++)
                ldm4(b1 + 4*j, sK1 + boff8 + j * 16 * K8STRIDE + sp * 32);
#pragma unroll
            for (int nt = 0; nt < 8; nt++) {
                mma_s8(acc0[nt], q0f[sp], b0 + 2*nt);
                mma_s8(acc1[nt], q0f[sp], b1 + 2*nt);
                mma_s8(acc1[nt], q1f[sp], b0 + 2*nt);
            }
        }

        // ---- dequant ----
        float s[8][4];
#pragma unroll
        for (int nt = 0; nt < 8; nt++) {
            float kc0 = skp[nt * 8 + (lane & 3) * 2];
            float kc1 = skp[nt * 8 + (lane & 3) * 2 + 1];
            s[nt][0] = sq0 * kc0 * ((float)acc0[nt][0] + (float)acc1[nt][0] * INV252);
            s[nt][1] = sq0 * kc1 * ((float)acc0[nt][1] + (float)acc1[nt][1] * INV252);
            s[nt][2] = sq1 * kc0 * ((float)acc0[nt][2] + (float)acc1[nt][2] * INV252);
            s[nt][3] = sq1 * kc1 * ((float)acc0[nt][3] + (float)acc1[nt][3] * INV252);
        }

        // ---- online softmax ----
        float tmax0 = -1e30f, tmax1 = -1e30f;
#pragma unroll
        for (int nt = 0; nt < 8; nt++) {
            tmax0 = fmaxf(tmax0, fmaxf(s[nt][0], s[nt][1]));
            tmax1 = fmaxf(tmax1, fmaxf(s[nt][2], s[nt][3]));
        }
        tmax0 = fmaxf(tmax0, __shfl_xor_sync(0xffffffffu, tmax0, 1));
        tmax0 = fmaxf(tmax0, __shfl_xor_sync(0xffffffffu, tmax0, 2));
        tmax1 = fmaxf(tmax1, __shfl_xor_sync(0xffffffffu, tmax1, 1));
        tmax1 = fmaxf(tmax1, __shfl_xor_sync(0xffffffffu, tmax1, 2));
        float nm0 = fmaxf(m0, tmax0), nm1 = fmaxf(m1, tmax1);
        float a0 = __expf(m0 - nm0), a1 = __expf(m1 - nm1);
        m0 = nm0; m1 = nm1;
        float ps0 = 0.f, ps1 = 0.f;
#pragma unroll
        for (int nt = 0; nt < 8; nt++) {
            s[nt][0] = __expf(s[nt][0] - m0);
            s[nt][1] = __expf(s[nt][1] - m0);
            s[nt][2] = __expf(s[nt][2] - m1);
            s[nt][3] = __expf(s[nt][3] - m1);
            ps0 += s[nt][0] + s[nt][1];
            ps1 += s[nt][2] + s[nt][3];
        }
        l0 = l0 * a0 + ps0;
        l1 = l1 * a1 + ps1;
#pragma unroll
        for (int nt = 0; nt < 8; nt++) {
            o_[nt][0] *= a0; o_[nt][1] *= a0;
            o_[nt][2] *= a1; o_[nt][3] *= a1;
        }

        // ---- PV: p fp16 x v fp16, single term ----
#pragma unroll
        for (int ks = 0; ks < 4; ks++) {
            uint32_t ph[4];
            ph[0] = packh(s[2*ks][0],   s[2*ks][1]);
            ph[1] = packh(s[2*ks][2],   s[2*ks][3]);
            ph[2] = packh(s[2*ks+1][0], s[2*ks+1][1]);
            ph[3] = packh(s[2*ks+1][2], s[2*ks+1][3]);
            uint32_t rbase = ks * 16 * 144;
#pragma unroll
            for (int n2 = 0; n2 < 4; n2++) {
                uint32_t vh[4];
                ldm4t(vh, sVh + voff + rbase + n2 * 32);
                mma_f16(o_[2*n2],     ph, vh + 0);
                mma_f16(o_[2*n2 + 1], ph, vh + 2);
            }
        }
        __syncthreads();
    }

    // ---- finalize: write single fp16 ----
    l0 += __shfl_xor_sync(0xffffffffu, l0, 1);
    l0 += __shfl_xor_sync(0xffffffffu, l0, 2);
    l1 += __shfl_xor_sync(0xffffffffu, l1, 1);
    l1 += __shfl_xor_sync(0xffffffffu, l1, 2);
    float inv0 = 1.f / l0, inv1 = 1.f / l1;

    int r = qbase + wq * 16 + (lane >> 2);
    int c = (lane & 3) * 2;
    size_t ob0 = ((size_t)(b * S + r) * HQ + h) * D;
    size_t ob1 = ((size_t)(b * S + r + 8) * HQ + h) * D;
#pragma unroll
    for (int nt = 0; nt < 8; nt++) {
        *(uint32_t*)(g_of + ob0 + nt * 8 + c) =
            packh(o_[nt][0] * inv0, o_[nt][1] * inv0);
        *(uint32_t*)(g_of + ob1 + nt * 8 + c) =
            packh(o_[nt][2] * inv1, o_[nt][3] * inv1);
    }
}

// ---------------------------------------------------------------------------
// Launch
// ---------------------------------------------------------------------------
extern "C" void kernel_launch(void* const* d_in, const int* in_sizes, int n_in,
                              void* d_out, int out_size)
{
    const float* x    = (const float*)d_in[0];
    const float* rcos = (const float*)d_in[1];
    const float* rsin = (const float*)d_in[2];
    const float* Wq   = (const float*)d_in[4];
    const float* Wk   = (const float*)d_in[5];
    const float* Wv   = (const float*)d_in[6];
    const float* Wo   = (const float*)d_in[7];
    float* out = (float*)d_out;

    float* qkvp;
    cudaGetSymbolAddress((void**)&qkvp, g_qkv);
    __nv_bfloat16 *xhi, *xlo, *wqkvhi, *wqkvlo;
    __half *wohf, *ofp;
    cudaGetSymbolAddress((void**)&xhi, g_xhi);
    cudaGetSymbolAddress((void**)&xlo, g_xlo);
    cudaGetSymbolAddress((void**)&wqkvhi, g_wqkvhi);
    cudaGetSymbolAddress((void**)&wqkvlo, g_wqkvlo);
    cudaGetSymbolAddress((void**)&wohf, g_wohf);
    cudaGetSymbolAddress((void**)&ofp, g_of);

    cudaFuncSetAttribute(mma_gemm_kernel,
                         cudaFuncAttributeMaxDynamicSharedMemorySize, GEMM_SMEM);
    cudaFuncSetAttribute(mma_gemm1_kernel,
                         cudaFuncAttributeMaxDynamicSharedMemorySize, GEMM1_SMEM);
    cudaFuncSetAttribute(flash_mma_kernel,
                         cudaFuncAttributeMaxDynamicSharedMemorySize, FLASH_SMEM);

    const int M = B * S;  // 4096

    // 0) split x
    {
        int n4 = M * E / 4;
        split_kernel<<<(n4 + 255) / 256, 256>>>(x, xhi, xlo, n4);
    }
    // 1-3) transpose+split Wq/Wk/Wv (bf16) into concatenated [3072, 2048]
    transpose_split_kernel<<<dim3((HQ*D)/32, E/32), dim3(32, 8)>>>(
        Wq, wqkvhi, wqkvlo, E, HQ*D);
    transpose_split_kernel<<<dim3((HK*D)/32, E/32), dim3(32, 8)>>>(
        Wk, wqkvhi + (size_t)2048 * E, wqkvlo + (size_t)2048 * E, E, HK*D);
    transpose_split_kernel<<<dim3((HK*D)/32, E/32), dim3(32, 8)>>>(
        Wv, wqkvhi + (size_t)2560 * E, wqkvlo + (size_t)2560 * E, E, HK*D);
    // 4) transpose Wo (single fp16)
    transpose_h_kernel<<<dim3(E/32, (HQ*D)/32), dim3(32, 8)>>>(
        Wo, wohf, HQ*D, E);

    // 5) fused QKV projection
    mma_gemm_kernel<<<dim3(3072/128, M/128), 256, GEMM_SMEM>>>(
        M, 3072, E, xhi, xlo, wqkvhi, wqkvlo, qkvp);

    // 6) fused RoPE + int8 quantize (warp per head-row)
    {
        int nwarps = B * S * 48;          // 196608
        rope_quant_kernel<<<nwarps / 8, 256>>>(qkvp, rcos, rsin);
    }

    // 7) tensor-core flash attention (int8 QK, fp16 PV)
    flash_mma_kernel<<<dim3(S / 128, HQ, B), 256, FLASH_SMEM>>>();

    // 8) O-projection (fp16, single term)
    mma_gemm1_kernel<<<dim3(E/128, M/128), 256, GEMM1_SMEM>>>(
        M, E, HQ*D, ofp, wohf, out);
}

// round 9
// speedup vs baseline: 1.0010x; 1.0010x over previous
#include <cuda_runtime.h>
#include <cuda_bf16.h>
#include <cuda_fp16.h>
#include <cstdint>

// Problem constants
#define B 2
#define S 2048
#define E 2048
#define HQ 32
#define HK 8
#define D 64

// ---------------------------------------------------------------------------
// Scratch (device globals)
// ---------------------------------------------------------------------------
__device__ float g_qkv[(size_t)B * S * 3072];            // fused QKV fp32

__device__ __nv_bfloat16 g_xhi[(size_t)B * S * E];
__device__ __nv_bfloat16 g_xlo[(size_t)B * S * E];
__device__ __nv_bfloat16 g_wqkvhi[(size_t)3072 * E];     // [N=3072, K=2048]
__device__ __nv_bfloat16 g_wqkvlo[(size_t)3072 * E];
__device__ __half        g_wohf[(size_t)E * HQ * D];     // Wo^T fp16 (single)

// int8 2-term quantized q/k (post-RoPE) + per-head-row scales
__device__ int8_t g_q0[(size_t)B * S * HQ * D];
__device__ int8_t g_q1[(size_t)B * S * HQ * D];
__device__ int8_t g_k0[(size_t)B * S * HK * D];
__device__ int8_t g_k1[(size_t)B * S * HK * D];
__device__ float  g_sq[(size_t)B * HQ * S];              // head-major
__device__ float  g_sk[(size_t)B * HK * S];              // head-major
__device__ __half g_vh[(size_t)B * S * HK * D];          // v fp16 (single)
__device__ __half g_of[(size_t)B * S * HQ * D];          // attention out, fp16

// ---------------------------------------------------------------------------
// PTX helpers (base-target safe)
// ---------------------------------------------------------------------------
__device__ __forceinline__ uint32_t smem_u32(const void* p) {
    uint32_t a;
    asm("{ .reg .u64 t; cvta.to.shared.u64 t, %1; cvt.u32.u64 %0, t; }"
        : "=r"(a) : "l"(p));
    return a;
}
__device__ __forceinline__ void cp16(uint32_t dst, const void* src) {
    asm volatile("cp.async.cg.shared.global [%0], [%1], 16;"
                 :: "r"(dst), "l"(src) : "memory");
}
__device__ __forceinline__ void cp_commit() {
    asm volatile("cp.async.commit_group;" ::: "memory");
}
template <int N>
__device__ __forceinline__ void cp_wait() {
    asm volatile("cp.async.wait_group %0;" :: "n"(N) : "memory");
}
__device__ __forceinline__ void ldm4(uint32_t* r, uint32_t addr) {
    asm volatile("ldmatrix.sync.aligned.m8n8.x4.shared.b16 {%0,%1,%2,%3}, [%4];"
                 : "=r"(r[0]), "=r"(r[1]), "=r"(r[2]), "=r"(r[3]) : "r"(addr));
}
__device__ __forceinline__ void ldm4t(uint32_t* r, uint32_t addr) {
    asm volatile("ldmatrix.sync.aligned.m8n8.x4.trans.shared.b16 {%0,%1,%2,%3}, [%4];"
                 : "=r"(r[0]), "=r"(r[1]), "=r"(r[2]), "=r"(r[3]) : "r"(addr));
}
__device__ __forceinline__ void mma_bf16(float* c, const uint32_t* a,
                                         const uint32_t* b) {
    asm volatile(
        "mma.sync.aligned.m16n8k16.row.col.f32.bf16.bf16.f32 "
        "{%0,%1,%2,%3}, {%4,%5,%6,%7}, {%8,%9}, {%0,%1,%2,%3};"
        : "+f"(c[0]), "+f"(c[1]), "+f"(c[2]), "+f"(c[3])
        : "r"(a[0]), "r"(a[1]), "r"(a[2]), "r"(a[3]), "r"(b[0]), "r"(b[1]));
}
__device__ __forceinline__ void mma_f16(float* c, const uint32_t* a,
                                        const uint32_t* b) {
    asm volatile(
        "mma.sync.aligned.m16n8k16.row.col.f32.f16.f16.f32 "
        "{%0,%1,%2,%3}, {%4,%5,%6,%7}, {%8,%9}, {%0,%1,%2,%3};"
        : "+f"(c[0]), "+f"(c[1]), "+f"(c[2]), "+f"(c[3])
        : "r"(a[0]), "r"(a[1]), "r"(a[2]), "r"(a[3]), "r"(b[0]), "r"(b[1]));
}
__device__ __forceinline__ void mma_s8(int* c, const uint32_t* a,
                                       const uint32_t* b) {
    asm volatile(
        "mma.sync.aligned.m16n8k32.row.col.s32.s8.s8.s32 "
        "{%0,%1,%2,%3}, {%4,%5,%6,%7}, {%8,%9}, {%0,%1,%2,%3};"
        : "+r"(c[0]), "+r"(c[1]), "+r"(c[2]), "+r"(c[3])
        : "r"(a[0]), "r"(a[1]), "r"(a[2]), "r"(a[3]), "r"(b[0]), "r"(b[1]));
}
__device__ __forceinline__ uint32_t packbf(__nv_bfloat16 a, __nv_bfloat16 b) {
    __nv_bfloat162 t = __halves2bfloat162(a, b);
    return *(uint32_t*)&t;
}
__device__ __forceinline__ uint32_t packh(float x, float y) {
    __half2 t = __floats2half2_rn(x, y);
    return *(uint32_t*)&t;
}
__device__ __forceinline__ void split2(float x, float y,
                                       uint32_t& hi, uint32_t& lo) {
    __nv_bfloat16 hx = __float2bfloat16(x), hy = __float2bfloat16(y);
    __nv_bfloat16 lx = __float2bfloat16(x - __bfloat162float(hx));
    __nv_bfloat16 ly = __float2bfloat16(y - __bfloat162float(hy));
    hi = packbf(hx, hy);
    lo = packbf(lx, ly);
}

// ---------------------------------------------------------------------------
// Split fp32 -> bf16 hi/lo
// ---------------------------------------------------------------------------
__global__ void split_kernel(const float* __restrict__ src,
                             __nv_bfloat16* __restrict__ hi,
                             __nv_bfloat16* __restrict__ lo, int n4)
{
    int i = blockIdx.x * blockDim.x + threadIdx.x;
    if (i >= n4) return;
    float4 v = ((const float4*)src)[i];
    uint32_t h0, l0, h1, l1;
    split2(v.x, v.y, h0, l0);
    split2(v.z, v.w, h1, l1);
    ((uint32_t*)hi)[2*i]   = h0;
    ((uint32_t*)hi)[2*i+1] = h1;
    ((uint32_t*)lo)[2*i]   = l0;
    ((uint32_t*)lo)[2*i+1] = l1;
}

// ---------------------------------------------------------------------------
// Transpose W[K,N] -> Wt[N,K], bf16 hi/lo
// ---------------------------------------------------------------------------
__global__ __launch_bounds__(256) void transpose_split_kernel(
    const float* __restrict__ W,
    __nv_bfloat16* __restrict__ hiT,
    __nv_bfloat16* __restrict__ loT, int K, int N)
{
    __shared__ float t[32][33];
    int n0 = blockIdx.x * 32, k0 = blockIdx.y * 32;
    int tx = threadIdx.x, ty = threadIdx.y;
#pragma unroll
    for (int r = 0; r < 4; r++)
        t[ty + r*8][tx] = W[(size_t)(k0 + ty + r*8) * N + n0 + tx];
    __syncthreads();
#pragma unroll
    for (int r = 0; r < 4; r++) {
        int n = n0 + ty + r*8;
        float v = t[tx][ty + r*8];
        __nv_bfloat16 h = __float2bfloat16(v);
        hiT[(size_t)n * K + k0 + tx] = h;
        loT[(size_t)n * K + k0 + tx] = __float2bfloat16(v - __bfloat162float(h));
    }
}

// Transpose W[K,N] -> Wt[N,K], single fp16
__global__ __launch_bounds__(256) void transpose_h_kernel(
    const float* __restrict__ W,
    __half* __restrict__ hT, int K, int N)
{
    __shared__ float t[32][33];
    int n0 = blockIdx.x * 32, k0 = blockIdx.y * 32;
    int tx = threadIdx.x, ty = threadIdx.y;
#pragma unroll
    for (int r = 0; r < 4; r++)
        t[ty + r*8][tx] = W[(size_t)(k0 + ty + r*8) * N + n0 + tx];
    __syncthreads();
#pragma unroll
    for (int r = 0; r < 4; r++) {
        int n = n0 + ty + r*8;
        hT[(size_t)n * K + k0 + tx] = __float2half_rn(t[tx][ty + r*8]);
    }
}

// ---------------------------------------------------------------------------
// mma.sync bf16 3-term GEMM (verified)
// ---------------------------------------------------------------------------
#define TSTRIDE 80
#define TILE_BYTES (128 * TSTRIDE)
#define STAGE_BYTES (4 * TILE_BYTES)
#define GEMM_SMEM (2 * STAGE_BYTES)

__device__ __forceinline__ void load_stage(
    uint32_t base, int tid,
    const __nv_bfloat16* Ah, const __nv_bfloat16* Al,
    const __nv_bfloat16* Bh, const __nv_bfloat16* Bl,
    int K, int k0)
{
    int ch = tid & 3;
    int rhalf = tid >> 2;
#pragma unroll
    for (int i = 0; i < 8; i++) {
        int tile = i >> 1;
        int row = (i & 1) * 64 + rhalf;
        uint32_t dst = base + tile * TILE_BYTES + row * TSTRIDE + ch * 16;
        const __nv_bfloat16* src =
            (tile == 0) ? Ah : (tile == 1) ? Al : (tile == 2) ? Bh : Bl;
        cp16(dst, src + (size_t)row * K + k0 + ch * 8);
    }
}

__global__ __launch_bounds__(256) void mma_gemm_kernel(
    int M, int N, int K,
    const __nv_bfloat16* __restrict__ Ahi, const __nv_bfloat16* __restrict__ Alo,
    const __nv_bfloat16* __restrict__ Bhi, const __nv_bfloat16* __restrict__ Blo,
    float* __restrict__ C)
{
    extern __shared__ char smem[];
    uint32_t sb = smem_u32(smem);
    int tid = threadIdx.x;
    int lane = tid & 31, wid = tid >> 5;
    int wm = wid & 1, wn = wid >> 1;
    int bm = blockIdx.y * 128, bn = blockIdx.x * 128;

    const __nv_bfloat16* Ah = Ahi + (size_t)bm * K;
    const __nv_bfloat16* Al = Alo + (size_t)bm * K;
    const __nv_bfloat16* Bh = Bhi + (size_t)bn * K;
    const __nv_bfloat16* Bl = Blo + (size_t)bn * K;

    float acc[4][4][4];
#pragma unroll
    for (int i = 0; i < 4; i++)
#pragma unroll
        for (int j = 0; j < 4; j++)
#pragma unroll
            for (int r = 0; r < 4; r++) acc[i][j][r] = 0.f;

    uint32_t aoff = (uint32_t)((wm * 64 + (lane & 15)) * TSTRIDE + (lane >> 4) * 16);
    uint32_t boff = (uint32_t)((wn * 32 + ((lane >> 4) * 8) + (lane & 7)) * TSTRIDE
                               + ((lane >> 3) & 1) * 16);

    const int nch = K >> 5;
    load_stage(sb, tid, Ah, Al, Bh, Bl, K, 0);
    cp_commit();

    for (int ch = 0; ch < nch; ch++) {
        if (ch + 1 < nch) {
            load_stage(sb + ((ch + 1) & 1) * STAGE_BYTES, tid,
                       Ah, Al, Bh, Bl, K, (ch + 1) << 5);
            cp_commit();
            cp_wait<1>();
        } else {
            cp_wait<0>();
        }
        __syncthreads();

        uint32_t st = sb + (ch & 1) * STAGE_BYTES;
        uint32_t sAhi = st;
        uint32_t sAlo = st + TILE_BYTES;
        uint32_t sBhi = st + 2 * TILE_BYTES;
        uint32_t sBlo = st + 3 * TILE_BYTES;

#pragma unroll
        for (int ks = 0; ks < 2; ks++) {
            uint32_t kb = ks * 32;
            uint32_t bh[8], bl[8], a[16];
            ldm4(bh + 0, sBhi + boff + kb);
            ldm4(bh + 4, sBhi + boff + 16 * TSTRIDE + kb);
            ldm4(bl + 0, sBlo + boff + kb);
            ldm4(bl + 4, sBlo + boff + 16 * TSTRIDE + kb);
#pragma unroll
            for (int mt = 0; mt < 4; mt++)
                ldm4(a + 4 * mt, sAhi + aoff + mt * 16 * TSTRIDE + kb);
#pragma unroll
            for (int mt = 0; mt < 4; mt++)
#pragma unroll
                for (int nt = 0; nt < 4; nt++)
                    mma_bf16(acc[mt][nt], a + 4 * mt, bh + 2 * nt);
#pragma unroll
            for (int mt = 0; mt < 4; mt++)
#pragma unroll
                for (int nt = 0; nt < 4; nt++)
                    mma_bf16(acc[mt][nt], a + 4 * mt, bl + 2 * nt);
#pragma unroll
            for (int mt = 0; mt < 4; mt++)
                ldm4(a + 4 * mt, sAlo + aoff + mt * 16 * TSTRIDE + kb);
#pragma unroll
            for (int mt = 0; mt < 4; mt++)
#pragma unroll
                for (int nt = 0; nt < 4; nt++)
                    mma_bf16(acc[mt][nt], a + 4 * mt, bh + 2 * nt);
        }
        __syncthreads();
    }

    int r0 = bm + wm * 64 + (lane >> 2);
    int c0 = bn + wn * 32 + (lane & 3) * 2;
#pragma unroll
    for (int mt = 0; mt < 4; mt++) {
#pragma unroll
        for (int nt = 0; nt < 4; nt++) {
            int row = r0 + mt * 16;
            int col = c0 + nt * 8;
            *(float2*)&C[(size_t)row * N + col] =
                make_float2(acc[mt][nt][0], acc[mt][nt][1]);
            *(float2*)&C[(size_t)(row + 8) * N + col] =
                make_float2(acc[mt][nt][2], acc[mt][nt][3]);
        }
    }
}

// ---------------------------------------------------------------------------
// fp16 single-term GEMM: C = A(fp16) * B^T(fp16).  2 staged tiles.
// ---------------------------------------------------------------------------
#define STAGE1_BYTES (2 * TILE_BYTES)
#define GEMM1_SMEM (2 * STAGE1_BYTES)

__device__ __forceinline__ void load_stage1(
    uint32_t base, int tid,
    const __half* A, const __half* Bh, int K, int k0)
{
    int ch = tid & 3;
    int rhalf = tid >> 2;
#pragma unroll
    for (int i = 0; i < 4; i++) {
        int tile = i >> 1;
        int row = (i & 1) * 64 + rhalf;
        uint32_t dst = base + tile * TILE_BYTES + row * TSTRIDE + ch * 16;
        const __half* src = (tile == 0) ? A : Bh;
        cp16(dst, src + (size_t)row * K + k0 + ch * 8);
    }
}

__global__ __launch_bounds__(256) void mma_gemm1_kernel(
    int M, int N, int K,
    const __half* __restrict__ A,
    const __half* __restrict__ Bhi,
    float* __restrict__ C)
{
    extern __shared__ char smem[];
    uint32_t sb = smem_u32(smem);
    int tid = threadIdx.x;
    int lane = tid & 31, wid = tid >> 5;
    int wm = wid & 1, wn = wid >> 1;
    int bm = blockIdx.y * 128, bn = blockIdx.x * 128;

    const __half* Ap = A + (size_t)bm * K;
    const __half* Bh = Bhi + (size_t)bn * K;

    float acc[4][4][4];
#pragma unroll
    for (int i = 0; i < 4; i++)
#pragma unroll
        for (int j = 0; j < 4; j++)
#pragma unroll
            for (int r = 0; r < 4; r++) acc[i][j][r] = 0.f;

    uint32_t aoff = (uint32_t)((wm * 64 + (lane & 15)) * TSTRIDE + (lane >> 4) * 16);
    uint32_t boff = (uint32_t)((wn * 32 + ((lane >> 4) * 8) + (lane & 7)) * TSTRIDE
                               + ((lane >> 3) & 1) * 16);

    const int nch = K >> 5;
    load_stage1(sb, tid, Ap, Bh, K, 0);
    cp_commit();

    for (int ch = 0; ch < nch; ch++) {
        if (ch + 1 < nch) {
            load_stage1(sb + ((ch + 1) & 1) * STAGE1_BYTES, tid,
                        Ap, Bh, K, (ch + 1) << 5);
            cp_commit();
            cp_wait<1>();
        } else {
            cp_wait<0>();
        }
        __syncthreads();

        uint32_t st = sb + (ch & 1) * STAGE1_BYTES;
        uint32_t sA = st;
        uint32_t sB = st + TILE_BYTES;

#pragma unroll
        for (int ks = 0; ks < 2; ks++) {
            uint32_t kb = ks * 32;
            uint32_t bh[8], a[16];
            ldm4(bh + 0, sB + boff + kb);
            ldm4(bh + 4, sB + boff + 16 * TSTRIDE + kb);
#pragma unroll
            for (int mt = 0; mt < 4; mt++)
                ldm4(a + 4 * mt, sA + aoff + mt * 16 * TSTRIDE + kb);
#pragma unroll
            for (int mt = 0; mt < 4; mt++)
#pragma unroll
                for (int nt = 0; nt < 4; nt++)
                    mma_f16(acc[mt][nt], a + 4 * mt, bh + 2 * nt);
        }
        __syncthreads();
    }

    int r0 = bm + wm * 64 + (lane >> 2);
    int c0 = bn + wn * 32 + (lane & 3) * 2;
#pragma unroll
    for (int mt = 0; mt < 4; mt++) {
#pragma unroll
        for (int nt = 0; nt < 4; nt++) {
            int row = r0 + mt * 16;
            int col = c0 + nt * 8;
            *(float2*)&C[(size_t)row * N + col] =
                make_float2(acc[mt][nt][0], acc[mt][nt][1]);
            *(float2*)&C[(size_t)(row + 8) * N + col] =
                make_float2(acc[mt][nt][2], acc[mt][nt][3]);
        }
    }
}

// ---------------------------------------------------------------------------
// Fused RoPE + quantize. One warp per head-row.
// q/k -> int8 2-term (x ≈ s·(a0 + a1/252)) + per-row scale; v -> fp16.
// heads 0-31: q, 32-39: k, 40-47: v.
// ---------------------------------------------------------------------------
__global__ __launch_bounds__(256) void rope_quant_kernel(
    const float* __restrict__ qkv,
    const float* __restrict__ cs,
    const float* __restrict__ sn)
{
    int gw = (blockIdx.x * 256 + threadIdx.x) >> 5;
    int lane = threadIdx.x & 31;
    int rowid = gw / 48;
    int head = gw - rowid * 48;
    int s = rowid & (S - 1);
    int b = rowid >> 11;

    const float* base;
    if (head < 32)      base = qkv + (size_t)rowid * 3072 + head * 64;
    else if (head < 40) base = qkv + (size_t)rowid * 3072 + 2048 + (head - 32) * 64;
    else                base = qkv + (size_t)rowid * 3072 + 2560 + (head - 40) * 64;
    float v1 = base[lane], v2 = base[lane + 32];

    if (head < 40) {
        float c = cs[s * 32 + lane], si = sn[s * 32 + lane];
        float r1 = v1 * c - v2 * si;
        float r2 = v2 * c + v1 * si;
        float mx = fmaxf(fabsf(r1), fabsf(r2));
#pragma unroll
        for (int o = 16; o; o >>= 1)
            mx = fmaxf(mx, __shfl_xor_sync(0xffffffffu, mx, o));
        float sc = mx * (1.f / 127.f);
        float inv = (mx > 0.f) ? 127.f / mx : 0.f;
        float t1 = r1 * inv, t2 = r2 * inv;
        int a1 = __float2int_rn(t1), a2 = __float2int_rn(t2);
        int c1 = __float2int_rn((t1 - (float)a1) * 252.f);
        int c2 = __float2int_rn((t2 - (float)a2) * 252.f);
        int8_t *d0, *d1;
        float* sdst;
        if (head < 32) {
            size_t o = ((size_t)rowid * HQ + head) * 64;
            d0 = g_q0 + o; d1 = g_q1 + o;
            sdst = g_sq + ((size_t)b * HQ + head) * S + s;
        } else {
            int h2 = head - 32;
            size_t o = ((size_t)rowid * HK + h2) * 64;
            d0 = g_k0 + o; d1 = g_k1 + o;
            sdst = g_sk + ((size_t)b * HK + h2) * S + s;
        }
        d0[lane] = (int8_t)a1; d0[lane + 32] = (int8_t)a2;
        d1[lane] = (int8_t)c1; d1[lane + 32] = (int8_t)c2;
        if (lane == 0) *sdst = sc;
    } else {
        int h2 = head - 40;
        size_t o = ((size_t)rowid * HK + h2) * 64;
        g_vh[o + lane] = __float2half_rn(v1);
        g_vh[o + lane + 32] = __float2half_rn(v2);
    }
}

// ---------------------------------------------------------------------------
// Tensor-core flash attention.
// QK: int8 2-term (s8 m16n8k32, groups hh + hl + lh). PV: fp16 single.
// ---------------------------------------------------------------------------
#define K8STRIDE 80
#define K8TILE (64 * K8STRIDE)          // 5120
#define V8OFF (2 * K8TILE)              // 10240
#define VTILE (64 * 144)                // 9216
#define SK8OFF (V8OFF + VTILE)          // 19456
#define FSTAGE8 (SK8OFF + 256)          // 19712
#define QT8 (128 * K8STRIDE)            // 10240
#define FLASH_SMEM (2 * FSTAGE8)        // 39424

__global__ __launch_bounds__(256) void flash_mma_kernel()
{
    extern __shared__ char smem[];
    uint32_t sb = smem_u32(smem);
    int tid = threadIdx.x;
    int lane = tid & 31, wq = tid >> 5;
    int qbase = blockIdx.x * 128;
    int h = blockIdx.y, b = blockIdx.z;
    int kh = h >> 2;

    // ---- stage Q int8 (q0, q1) and build fragments ----
#pragma unroll
    for (int i = 0; i < 4; i++) {
        int lin = i * 256 + tid;
        int arr = lin >> 9;
        int rem = lin & 511;
        int row = rem >> 2;
        int seg = rem & 3;
        const int8_t* src = (arr ? g_q1 : g_q0)
            + ((size_t)(b * S + qbase + row) * HQ + h) * 64 + seg * 16;
        cp16(sb + arr * QT8 + row * K8STRIDE + seg * 16, src);
    }
    cp_commit();
    cp_wait<0>();
    __syncthreads();

    uint32_t q0f[2][4], q1f[2][4];
    {
        uint32_t qoff = (uint32_t)((wq * 16 + (lane & 15)) * K8STRIDE + (lane >> 4) * 16);
#pragma unroll
        for (int sp = 0; sp < 2; sp++) {
            ldm4(q0f[sp], sb + qoff + sp * 32);
            ldm4(q1f[sp], sb + QT8 + qoff + sp * 32);
        }
    }
    float sq0 = g_sq[((size_t)b * HQ + h) * S + qbase + wq * 16 + (lane >> 2)];
    float sq1 = g_sq[((size_t)b * HQ + h) * S + qbase + wq * 16 + (lane >> 2) + 8];
    __syncthreads();

    // ---- kv staging ----
    const int8_t* k0src = g_k0 + ((size_t)b * S * HK + kh) * 64;
    const int8_t* k1src = g_k1 + ((size_t)b * S * HK + kh) * 64;
    const uint8_t* vsrc = (const uint8_t*)(g_vh + ((size_t)b * S * HK + kh) * D);
    const uint8_t* sksrc = (const uint8_t*)(g_sk + ((size_t)b * HK + kh) * S);

    auto prefetch = [&](int t) {
        uint32_t base = sb + (t & 1) * FSTAGE8;
        int key0 = t * 64;
        // k0/k1 tiles: 64 rows x 64B, stride 80
#pragma unroll
        for (int i = 0; i < 2; i++) {
            int lin = i * 256 + tid;
            int arr = lin >> 8;
            int rem = lin & 255;
            int row = rem >> 2;
            int seg = rem & 3;
            const int8_t* src = (arr ? k1src : k0src)
                + (size_t)(key0 + row) * (HK * 64) + seg * 16;
            cp16(base + arr * K8TILE + row * K8STRIDE + seg * 16, src);
        }
        // v tile: 64 rows x 128B, stride 144
#pragma unroll
        for (int i = 0; i < 2; i++) {
            int lin = i * 256 + tid;
            int row = lin >> 3;
            int seg = lin & 7;
            cp16(base + V8OFF + row * 144 + seg * 16,
                 vsrc + (size_t)(key0 + row) * (HK * D * 2) + seg * 16);
        }
        // sk: 64 floats
        if (tid < 16)
            cp16(base + SK8OFF + tid * 16, sksrc + (size_t)key0 * 4 + tid * 16);
        cp_commit();
    };

    uint32_t boff8 = (uint32_t)(((lane >> 4) * 8 + (lane & 7)) * K8STRIDE
                                + ((lane >> 3) & 1) * 16);
    uint32_t voff = (uint32_t)((lane & 15) * 144 + (lane >> 4) * 16);

    float o_[8][4];
#pragma unroll
    for (int nt = 0; nt < 8; nt++)
#pragma unroll
        for (int r = 0; r < 4; r++) o_[nt][r] = 0.f;
    float m0 = -1e30f, m1 = -1e30f, l0 = 0.f, l1 = 0.f;

    prefetch(0);

    const float INV252 = 1.f / 252.f;
    const int NT = S / 64;
    for (int t = 0; t < NT; t++) {
        if (t + 1 < NT) { prefetch(t + 1); cp_wait<1>(); }
        else           { cp_wait<0>(); }
        __syncthreads();

        uint32_t st = sb + (t & 1) * FSTAGE8;
        uint32_t sK0 = st, sK1 = st + K8TILE;
        uint32_t sVh = st + V8OFF;
        const float* skp = (const float*)(smem + (size_t)(t & 1) * FSTAGE8 + SK8OFF);

        // ---- QK int8: acc0 = q0k0, acc1 = q0k1 + q1k0 ----
        int acc0[8][4], acc1[8][4];
#pragma unroll
        for (int nt = 0; nt < 8; nt++)
#pragma unroll
            for (int r = 0; r < 4; r++) { acc0[nt][r] = 0; acc1[nt][r] = 0; }

#pragma unroll
        for (int sp = 0; sp < 2; sp++) {
            uint32_t b0[16], b1[16];
#pragma unroll
            for (int j = 0; j < 4; j++)
                ldm4(b0 + 4*j, sK0 + boff8 + j * 16 * K8STRIDE + sp * 32);
#pragma unroll
            for (int j = 0; j < 4; j++)
                ldm4(b1 + 4*j, sK1 + boff8 + j * 16 * K8STRIDE + sp * 32);
#pragma unroll
            for (int nt = 0; nt < 8; nt++) {
                mma_s8(acc0[nt], q0f[sp], b0 + 2*nt);
                mma_s8(acc1[nt], q0f[sp], b1 + 2*nt);
                mma_s8(acc1[nt], q1f[sp], b0 + 2*nt);
            }
        }

        // ---- dequant ----
        float s[8][4];
#pragma unroll
        for (int nt = 0; nt < 8; nt++) {
            float kc0 = skp[nt * 8 + (lane & 3) * 2];
            float kc1 = skp[nt * 8 + (lane & 3) * 2 + 1];
            s[nt][0] = sq0 * kc0 * ((float)acc0[nt][0] + (float)acc1[nt][0] * INV252);
            s[nt][1] = sq0 * kc1 * ((float)acc0[nt][1] + (float)acc1[nt][1] * INV252);
            s[nt][2] = sq1 * kc0 * ((float)acc0[nt][2] + (float)acc1[nt][2] * INV252);
            s[nt][3] = sq1 * kc1 * ((float)acc0[nt][3] + (float)acc1[nt][3] * INV252);
        }

        // ---- online softmax ----
        float tmax0 = -1e30f, tmax1 = -1e30f;
#pragma unroll
        for (int nt = 0; nt < 8; nt++) {
            tmax0 = fmaxf(tmax0, fmaxf(s[nt][0], s[nt][1]));
            tmax1 = fmaxf(tmax1, fmaxf(s[nt][2], s[nt][3]));
        }
        tmax0 = fmaxf(tmax0, __shfl_xor_sync(0xffffffffu, tmax0, 1));
        tmax0 = fmaxf(tmax0, __shfl_xor_sync(0xffffffffu, tmax0, 2));
        tmax1 = fmaxf(tmax1, __shfl_xor_sync(0xffffffffu, tmax1, 1));
        tmax1 = fmaxf(tmax1, __shfl_xor_sync(0xffffffffu, tmax1, 2));
        float nm0 = fmaxf(m0, tmax0), nm1 = fmaxf(m1, tmax1);
        float a0 = __expf(m0 - nm0), a1 = __expf(m1 - nm1);
        m0 = nm0; m1 = nm1;
        float ps0 = 0.f, ps1 = 0.f;
#pragma unroll
        for (int nt = 0; nt < 8; nt++) {
            s[nt][0] = __expf(s[nt][0] - m0);
            s[nt][1] = __expf(s[nt][1] - m0);
            s[nt][2] = __expf(s[nt][2] - m1);
            s[nt][3] = __expf(s[nt][3] - m1);
            ps0 += s[nt][0] + s[nt][1];
            ps1 += s[nt][2] + s[nt][3];
        }
        l0 = l0 * a0 + ps0;
        l1 = l1 * a1 + ps1;
#pragma unroll
        for (int nt = 0; nt < 8; nt++) {
            o_[nt][0] *= a0; o_[nt][1] *= a0;
            o_[nt][2] *= a1; o_[nt][3] *= a1;
        }

        // ---- PV: p fp16 x v fp16, single term ----
#pragma unroll
        for (int ks = 0; ks < 4; ks++) {
            uint32_t ph[4];
            ph[0] = packh(s[2*ks][0],   s[2*ks][1]);
            ph[1] = packh(s[2*ks][2],   s[2*ks][3]);
            ph[2] = packh(s[2*ks+1][0], s[2*ks+1][1]);
            ph[3] = packh(s[2*ks+1][2], s[2*ks+1][3]);
            uint32_t rbase = ks * 16 * 144;
#pragma unroll
            for (int n2 = 0; n2 < 4; n2++) {
                uint32_t vh[4];
                ldm4t(vh, sVh + voff + rbase + n2 * 32);
                mma_f16(o_[2*n2],     ph, vh + 0);
                mma_f16(o_[2*n2 + 1], ph, vh + 2);
            }
        }
        __syncthreads();
    }

    // ---- finalize: write single fp16 ----
    l0 += __shfl_xor_sync(0xffffffffu, l0, 1);
    l0 += __shfl_xor_sync(0xffffffffu, l0, 2);
    l1 += __shfl_xor_sync(0xffffffffu, l1, 1);
    l1 += __shfl_xor_sync(0xffffffffu, l1, 2);
    float inv0 = 1.f / l0, inv1 = 1.f / l1;

    int r = qbase + wq * 16 + (lane >> 2);
    int c = (lane & 3) * 2;
    size_t ob0 = ((size_t)(b * S + r) * HQ + h) * D;
    size_t ob1 = ((size_t)(b * S + r + 8) * HQ + h) * D;
#pragma unroll
    for (int nt = 0; nt < 8; nt++) {
        *(uint32_t*)(g_of + ob0 + nt * 8 + c) =
            packh(o_[nt][0] * inv0, o_[nt][1] * inv0);
        *(uint32_t*)(g_of + ob1 + nt * 8 + c) =
            packh(o_[nt][2] * inv1, o_[nt][3] * inv1);
    }
}

// ---------------------------------------------------------------------------
// Launch
// ---------------------------------------------------------------------------
extern "C" void kernel_launch(void* const* d_in, const int* in_sizes, int n_in,
                              void* d_out, int out_size)
{
    const float* x    = (const float*)d_in[0];
    const float* rcos = (const float*)d_in[1];
    const float* rsin = (const float*)d_in[2];
    const float* Wq   = (const float*)d_in[4];
    const float* Wk   = (const float*)d_in[5];
    const float* Wv   = (const float*)d_in[6];
    const float* Wo   = (const float*)d_in[7];
    float* out = (float*)d_out;

    float* qkvp;
    cudaGetSymbolAddress((void**)&qkvp, g_qkv);
    __nv_bfloat16 *xhi, *xlo, *wqkvhi, *wqkvlo;
    __half *wohf, *ofp;
    cudaGetSymbolAddress((void**)&xhi, g_xhi);
    cudaGetSymbolAddress((void**)&xlo, g_xlo);
    cudaGetSymbolAddress((void**)&wqkvhi, g_wqkvhi);
    cudaGetSymbolAddress((void**)&wqkvlo, g_wqkvlo);
    cudaGetSymbolAddress((void**)&wohf, g_wohf);
    cudaGetSymbolAddress((void**)&ofp, g_of);

    cudaFuncSetAttribute(mma_gemm_kernel,
                         cudaFuncAttributeMaxDynamicSharedMemorySize, GEMM_SMEM);
    cudaFuncSetAttribute(mma_gemm1_kernel,
                         cudaFuncAttributeMaxDynamicSharedMemorySize, GEMM1_SMEM);
    cudaFuncSetAttribute(flash_mma_kernel,
                         cudaFuncAttributeMaxDynamicSharedMemorySize, FLASH_SMEM);

    const int M = B * S;  // 4096

    // 0) split x
    {
        int n4 = M * E / 4;
        split_kernel<<<(n4 + 255) / 256, 256>>>(x, xhi, xlo, n4);
    }
    // 1-3) transpose+split Wq/Wk/Wv (bf16) into concatenated [3072, 2048]
    transpose_split_kernel<<<dim3((HQ*D)/32, E/32), dim3(32, 8)>>>(
        Wq, wqkvhi, wqkvlo, E, HQ*D);
    transpose_split_kernel<<<dim3((HK*D)/32, E/32), dim3(32, 8)>>>(
        Wk, wqkvhi + (size_t)2048 * E, wqkvlo + (size_t)2048 * E, E, HK*D);
    transpose_split_kernel<<<dim3((HK*D)/32, E/32), dim3(32, 8)>>>(
        Wv, wqkvhi + (size_t)2560 * E, wqkvlo + (size_t)2560 * E, E, HK*D);
    // 4) transpose Wo (single fp16)
    transpose_h_kernel<<<dim3(E/32, (HQ*D)/32), dim3(32, 8)>>>(
        Wo, wohf, HQ*D, E);

    // 5) fused QKV projection
    mma_gemm_kernel<<<dim3(3072/128, M/128), 256, GEMM_SMEM>>>(
        M, 3072, E, xhi, xlo, wqkvhi, wqkvlo, qkvp);

    // 6) fused RoPE + int8 quantize (warp per head-row)
    {
        int nwarps = B * S * 48;          // 196608
        rope_quant_kernel<<<nwarps / 8, 256>>>(qkvp, rcos, rsin);
    }

    // 7) tensor-core flash attention (int8 QK, fp16 PV)
    flash_mma_kernel<<<dim3(S / 128, HQ, B), 256, FLASH_SMEM>>>();

    // 8) O-projection (fp16, single term)
    mma_gemm1_kernel<<<dim3(E/128, M/128), 256, GEMM1_SMEM>>>(
        M, E, HQ*D, ofp, wohf, out);
}

// round 10
// speedup vs baseline: 1.4725x; 1.4710x over previous
#include <cuda_runtime.h>
#include <cuda_bf16.h>
#include <cuda_fp16.h>
#include <cstdint>

// Problem constants
#define B 2
#define S 2048
#define E 2048
#define HQ 32
#define HK 8
#define D 64

// ---------------------------------------------------------------------------
// Scratch (device globals)
// ---------------------------------------------------------------------------
__device__ float g_qk[(size_t)B * S * 2560];             // fused Q|K fp32

__device__ __nv_bfloat16 g_xhi[(size_t)B * S * E];
__device__ __nv_bfloat16 g_xlo[(size_t)B * S * E];
__device__ __half        g_xh[(size_t)B * S * E];        // x fp16 (for v-proj)
__device__ __nv_bfloat16 g_wqkhi[(size_t)2560 * E];      // [N=2560, K=2048]
__device__ __nv_bfloat16 g_wqklo[(size_t)2560 * E];
__device__ __half        g_wvh[(size_t)512 * E];         // Wv^T fp16
__device__ __half        g_wohf[(size_t)E * HQ * D];     // Wo^T fp16

__device__ __nv_bfloat16 g_qhi[(size_t)B * S * HQ * D]; // post-RoPE bf16
__device__ __nv_bfloat16 g_qlo[(size_t)B * S * HQ * D];
__device__ __nv_bfloat16 g_khi[(size_t)B * S * HK * D];
__device__ __nv_bfloat16 g_klo[(size_t)B * S * HK * D];
__device__ __half        g_vh[(size_t)B * S * HK * D];  // v fp16 (from GEMM)
__device__ __half        g_of[(size_t)B * S * HQ * D];  // attention out, fp16

// ---------------------------------------------------------------------------
// PTX helpers (base-target safe)
// ---------------------------------------------------------------------------
__device__ __forceinline__ uint32_t smem_u32(const void* p) {
    uint32_t a;
    asm("{ .reg .u64 t; cvta.to.shared.u64 t, %1; cvt.u32.u64 %0, t; }"
        : "=r"(a) : "l"(p));
    return a;
}
__device__ __forceinline__ void cp16(uint32_t dst, const void* src) {
    asm volatile("cp.async.cg.shared.global [%0], [%1], 16;"
                 :: "r"(dst), "l"(src) : "memory");
}
__device__ __forceinline__ void cp_commit() {
    asm volatile("cp.async.commit_group;" ::: "memory");
}
template <int N>
__device__ __forceinline__ void cp_wait() {
    asm volatile("cp.async.wait_group %0;" :: "n"(N) : "memory");
}
__device__ __forceinline__ void ldm4(uint32_t* r, uint32_t addr) {
    asm volatile("ldmatrix.sync.aligned.m8n8.x4.shared.b16 {%0,%1,%2,%3}, [%4];"
                 : "=r"(r[0]), "=r"(r[1]), "=r"(r[2]), "=r"(r[3]) : "r"(addr));
}
__device__ __forceinline__ void ldm4t(uint32_t* r, uint32_t addr) {
    asm volatile("ldmatrix.sync.aligned.m8n8.x4.trans.shared.b16 {%0,%1,%2,%3}, [%4];"
                 : "=r"(r[0]), "=r"(r[1]), "=r"(r[2]), "=r"(r[3]) : "r"(addr));
}
__device__ __forceinline__ void mma_bf16(float* c, const uint32_t* a,
                                         const uint32_t* b) {
    asm volatile(
        "mma.sync.aligned.m16n8k16.row.col.f32.bf16.bf16.f32 "
        "{%0,%1,%2,%3}, {%4,%5,%6,%7}, {%8,%9}, {%0,%1,%2,%3};"
        : "+f"(c[0]), "+f"(c[1]), "+f"(c[2]), "+f"(c[3])
        : "r"(a[0]), "r"(a[1]), "r"(a[2]), "r"(a[3]), "r"(b[0]), "r"(b[1]));
}
__device__ __forceinline__ void mma_f16(float* c, const uint32_t* a,
                                        const uint32_t* b) {
    asm volatile(
        "mma.sync.aligned.m16n8k16.row.col.f32.f16.f16.f32 "
        "{%0,%1,%2,%3}, {%4,%5,%6,%7}, {%8,%9}, {%0,%1,%2,%3};"
        : "+f"(c[0]), "+f"(c[1]), "+f"(c[2]), "+f"(c[3])
        : "r"(a[0]), "r"(a[1]), "r"(a[2]), "r"(a[3]), "r"(b[0]), "r"(b[1]));
}
__device__ __forceinline__ uint32_t packbf(__nv_bfloat16 a, __nv_bfloat16 b) {
    __nv_bfloat162 t = __halves2bfloat162(a, b);
    return *(uint32_t*)&t;
}
__device__ __forceinline__ uint32_t packh(float x, float y) {
    __half2 t = __floats2half2_rn(x, y);
    return *(uint32_t*)&t;
}
__device__ __forceinline__ void split2(float x, float y,
                                       uint32_t& hi, uint32_t& lo) {
    __nv_bfloat16 hx = __float2bfloat16(x), hy = __float2bfloat16(y);
    __nv_bfloat16 lx = __float2bfloat16(x - __bfloat162float(hx));
    __nv_bfloat16 ly = __float2bfloat16(y - __bfloat162float(hy));
    hi = packbf(hx, hy);
    lo = packbf(lx, ly);
}
__device__ __forceinline__ void splitf(float x, __nv_bfloat16& h, __nv_bfloat16& l) {
    h = __float2bfloat16(x);
    l = __float2bfloat16(x - __bfloat162float(h));
}

// ---------------------------------------------------------------------------
// Split fp32 -> bf16 hi/lo + fp16 single
// ---------------------------------------------------------------------------
__global__ void split3_kernel(const float* __restrict__ src,
                              __nv_bfloat16* __restrict__ hi,
                              __nv_bfloat16* __restrict__ lo,
                              __half* __restrict__ hf, int n4)
{
    int i = blockIdx.x * blockDim.x + threadIdx.x;
    if (i >= n4) return;
    float4 v = ((const float4*)src)[i];
    uint32_t h0, l0, h1, l1;
    split2(v.x, v.y, h0, l0);
    split2(v.z, v.w, h1, l1);
    ((uint32_t*)hi)[2*i]   = h0;
    ((uint32_t*)hi)[2*i+1] = h1;
    ((uint32_t*)lo)[2*i]   = l0;
    ((uint32_t*)lo)[2*i+1] = l1;
    ((uint32_t*)hf)[2*i]   = packh(v.x, v.y);
    ((uint32_t*)hf)[2*i+1] = packh(v.z, v.w);
}

// ---------------------------------------------------------------------------
// Transpose W[K,N] -> Wt[N,K], bf16 hi/lo
// ---------------------------------------------------------------------------
__global__ __launch_bounds__(256) void transpose_split_kernel(
    const float* __restrict__ W,
    __nv_bfloat16* __restrict__ hiT,
    __nv_bfloat16* __restrict__ loT, int K, int N)
{
    __shared__ float t[32][33];
    int n0 = blockIdx.x * 32, k0 = blockIdx.y * 32;
    int tx = threadIdx.x, ty = threadIdx.y;
#pragma unroll
    for (int r = 0; r < 4; r++)
        t[ty + r*8][tx] = W[(size_t)(k0 + ty + r*8) * N + n0 + tx];
    __syncthreads();
#pragma unroll
    for (int r = 0; r < 4; r++) {
        int n = n0 + ty + r*8;
        float v = t[tx][ty + r*8];
        __nv_bfloat16 h = __float2bfloat16(v);
        hiT[(size_t)n * K + k0 + tx] = h;
        loT[(size_t)n * K + k0 + tx] = __float2bfloat16(v - __bfloat162float(h));
    }
}

// Transpose W[K,N] -> Wt[N,K], single fp16
__global__ __launch_bounds__(256) void transpose_h_kernel(
    const float* __restrict__ W,
    __half* __restrict__ hT, int K, int N)
{
    __shared__ float t[32][33];
    int n0 = blockIdx.x * 32, k0 = blockIdx.y * 32;
    int tx = threadIdx.x, ty = threadIdx.y;
#pragma unroll
    for (int r = 0; r < 4; r++)
        t[ty + r*8][tx] = W[(size_t)(k0 + ty + r*8) * N + n0 + tx];
    __syncthreads();
#pragma unroll
    for (int r = 0; r < 4; r++) {
        int n = n0 + ty + r*8;
        hT[(size_t)n * K + k0 + tx] = __float2half_rn(t[tx][ty + r*8]);
    }
}

// ---------------------------------------------------------------------------
// mma.sync bf16 3-term GEMM (verified)
// ---------------------------------------------------------------------------
#define TSTRIDE 80
#define TILE_BYTES (128 * TSTRIDE)
#define STAGE_BYTES (4 * TILE_BYTES)
#define GEMM_SMEM (2 * STAGE_BYTES)

__device__ __forceinline__ void load_stage(
    uint32_t base, int tid,
    const __nv_bfloat16* Ah, const __nv_bfloat16* Al,
    const __nv_bfloat16* Bh, const __nv_bfloat16* Bl,
    int K, int k0)
{
    int ch = tid & 3;
    int rhalf = tid >> 2;
#pragma unroll
    for (int i = 0; i < 8; i++) {
        int tile = i >> 1;
        int row = (i & 1) * 64 + rhalf;
        uint32_t dst = base + tile * TILE_BYTES + row * TSTRIDE + ch * 16;
        const __nv_bfloat16* src =
            (tile == 0) ? Ah : (tile == 1) ? Al : (tile == 2) ? Bh : Bl;
        cp16(dst, src + (size_t)row * K + k0 + ch * 8);
    }
}

__global__ __launch_bounds__(256) void mma_gemm_kernel(
    int M, int N, int K,
    const __nv_bfloat16* __restrict__ Ahi, const __nv_bfloat16* __restrict__ Alo,
    const __nv_bfloat16* __restrict__ Bhi, const __nv_bfloat16* __restrict__ Blo,
    float* __restrict__ C)
{
    extern __shared__ char smem[];
    uint32_t sb = smem_u32(smem);
    int tid = threadIdx.x;
    int lane = tid & 31, wid = tid >> 5;
    int wm = wid & 1, wn = wid >> 1;
    int bm = blockIdx.y * 128, bn = blockIdx.x * 128;

    const __nv_bfloat16* Ah = Ahi + (size_t)bm * K;
    const __nv_bfloat16* Al = Alo + (size_t)bm * K;
    const __nv_bfloat16* Bh = Bhi + (size_t)bn * K;
    const __nv_bfloat16* Bl = Blo + (size_t)bn * K;

    float acc[4][4][4];
#pragma unroll
    for (int i = 0; i < 4; i++)
#pragma unroll
        for (int j = 0; j < 4; j++)
#pragma unroll
            for (int r = 0; r < 4; r++) acc[i][j][r] = 0.f;

    uint32_t aoff = (uint32_t)((wm * 64 + (lane & 15)) * TSTRIDE + (lane >> 4) * 16);
    uint32_t boff = (uint32_t)((wn * 32 + ((lane >> 4) * 8) + (lane & 7)) * TSTRIDE
                               + ((lane >> 3) & 1) * 16);

    const int nch = K >> 5;
    load_stage(sb, tid, Ah, Al, Bh, Bl, K, 0);
    cp_commit();

    for (int ch = 0; ch < nch; ch++) {
        if (ch + 1 < nch) {
            load_stage(sb + ((ch + 1) & 1) * STAGE_BYTES, tid,
                       Ah, Al, Bh, Bl, K, (ch + 1) << 5);
            cp_commit();
            cp_wait<1>();
        } else {
            cp_wait<0>();
        }
        __syncthreads();

        uint32_t st = sb + (ch & 1) * STAGE_BYTES;
        uint32_t sAhi = st;
        uint32_t sAlo = st + TILE_BYTES;
        uint32_t sBhi = st + 2 * TILE_BYTES;
        uint32_t sBlo = st + 3 * TILE_BYTES;

#pragma unroll
        for (int ks = 0; ks < 2; ks++) {
            uint32_t kb = ks * 32;
            uint32_t bh[8], bl[8], a[16];
            ldm4(bh + 0, sBhi + boff + kb);
            ldm4(bh + 4, sBhi + boff + 16 * TSTRIDE + kb);
            ldm4(bl + 0, sBlo + boff + kb);
            ldm4(bl + 4, sBlo + boff + 16 * TSTRIDE + kb);
#pragma unroll
            for (int mt = 0; mt < 4; mt++)
                ldm4(a + 4 * mt, sAhi + aoff + mt * 16 * TSTRIDE + kb);
#pragma unroll
            for (int mt = 0; mt < 4; mt++)
#pragma unroll
                for (int nt = 0; nt < 4; nt++)
                    mma_bf16(acc[mt][nt], a + 4 * mt, bh + 2 * nt);
#pragma unroll
            for (int mt = 0; mt < 4; mt++)
#pragma unroll
                for (int nt = 0; nt < 4; nt++)
                    mma_bf16(acc[mt][nt], a + 4 * mt, bl + 2 * nt);
#pragma unroll
            for (int mt = 0; mt < 4; mt++)
                ldm4(a + 4 * mt, sAlo + aoff + mt * 16 * TSTRIDE + kb);
#pragma unroll
            for (int mt = 0; mt < 4; mt++)
#pragma unroll
                for (int nt = 0; nt < 4; nt++)
                    mma_bf16(acc[mt][nt], a + 4 * mt, bh + 2 * nt);
        }
        __syncthreads();
    }

    int r0 = bm + wm * 64 + (lane >> 2);
    int c0 = bn + wn * 32 + (lane & 3) * 2;
#pragma unroll
    for (int mt = 0; mt < 4; mt++) {
#pragma unroll
        for (int nt = 0; nt < 4; nt++) {
            int row = r0 + mt * 16;
            int col = c0 + nt * 8;
            *(float2*)&C[(size_t)row * N + col] =
                make_float2(acc[mt][nt][0], acc[mt][nt][1]);
            *(float2*)&C[(size_t)(row + 8) * N + col] =
                make_float2(acc[mt][nt][2], acc[mt][nt][3]);
        }
    }
}

// ---------------------------------------------------------------------------
// fp16 single-term GEMM, fp32 output (O-projection)
// ---------------------------------------------------------------------------
#define STAGE1_BYTES (2 * TILE_BYTES)
#define GEMM1_SMEM (2 * STAGE1_BYTES)

__device__ __forceinline__ void load_stage1(
    uint32_t base, int tid,
    const __half* A, const __half* Bh, int K, int k0)
{
    int ch = tid & 3;
    int rhalf = tid >> 2;
#pragma unroll
    for (int i = 0; i < 4; i++) {
        int tile = i >> 1;
        int row = (i & 1) * 64 + rhalf;
        uint32_t dst = base + tile * TILE_BYTES + row * TSTRIDE + ch * 16;
        const __half* src = (tile == 0) ? A : Bh;
        cp16(dst, src + (size_t)row * K + k0 + ch * 8);
    }
}

template <bool HALF_OUT>
__global__ __launch_bounds__(256) void mma_gemm1_kernel(
    int M, int N, int K,
    const __half* __restrict__ A,
    const __half* __restrict__ Bhi,
    void* __restrict__ Cout)
{
    extern __shared__ char smem[];
    uint32_t sb = smem_u32(smem);
    int tid = threadIdx.x;
    int lane = tid & 31, wid = tid >> 5;
    int wm = wid & 1, wn = wid >> 1;
    int bm = blockIdx.y * 128, bn = blockIdx.x * 128;

    const __half* Ap = A + (size_t)bm * K;
    const __half* Bh = Bhi + (size_t)bn * K;

    float acc[4][4][4];
#pragma unroll
    for (int i = 0; i < 4; i++)
#pragma unroll
        for (int j = 0; j < 4; j++)
#pragma unroll
            for (int r = 0; r < 4; r++) acc[i][j][r] = 0.f;

    uint32_t aoff = (uint32_t)((wm * 64 + (lane & 15)) * TSTRIDE + (lane >> 4) * 16);
    uint32_t boff = (uint32_t)((wn * 32 + ((lane >> 4) * 8) + (lane & 7)) * TSTRIDE
                               + ((lane >> 3) & 1) * 16);

    const int nch = K >> 5;
    load_stage1(sb, tid, Ap, Bh, K, 0);
    cp_commit();

    for (int ch = 0; ch < nch; ch++) {
        if (ch + 1 < nch) {
            load_stage1(sb + ((ch + 1) & 1) * STAGE1_BYTES, tid,
                        Ap, Bh, K, (ch + 1) << 5);
            cp_commit();
            cp_wait<1>();
        } else {
            cp_wait<0>();
        }
        __syncthreads();

        uint32_t st = sb + (ch & 1) * STAGE1_BYTES;
        uint32_t sA = st;
        uint32_t sB = st + TILE_BYTES;

#pragma unroll
        for (int ks = 0; ks < 2; ks++) {
            uint32_t kb = ks * 32;
            uint32_t bh[8], a[16];
            ldm4(bh + 0, sB + boff + kb);
            ldm4(bh + 4, sB + boff + 16 * TSTRIDE + kb);
#pragma unroll
            for (int mt = 0; mt < 4; mt++)
                ldm4(a + 4 * mt, sA + aoff + mt * 16 * TSTRIDE + kb);
#pragma unroll
            for (int mt = 0; mt < 4; mt++)
#pragma unroll
                for (int nt = 0; nt < 4; nt++)
                    mma_f16(acc[mt][nt], a + 4 * mt, bh + 2 * nt);
        }
        __syncthreads();
    }

    int r0 = bm + wm * 64 + (lane >> 2);
    int c0 = bn + wn * 32 + (lane & 3) * 2;
#pragma unroll
    for (int mt = 0; mt < 4; mt++) {
#pragma unroll
        for (int nt = 0; nt < 4; nt++) {
            int row = r0 + mt * 16;
            int col = c0 + nt * 8;
            if (HALF_OUT) {
                __half* C = (__half*)Cout;
                *(uint32_t*)&C[(size_t)row * N + col] =
                    packh(acc[mt][nt][0], acc[mt][nt][1]);
                *(uint32_t*)&C[(size_t)(row + 8) * N + col] =
                    packh(acc[mt][nt][2], acc[mt][nt][3]);
            } else {
                float* C = (float*)Cout;
                *(float2*)&C[(size_t)row * N + col] =
                    make_float2(acc[mt][nt][0], acc[mt][nt][1]);
                *(float2*)&C[(size_t)(row + 8) * N + col] =
                    make_float2(acc[mt][nt][2], acc[mt][nt][3]);
            }
        }
    }
}

// ---------------------------------------------------------------------------
// Fused RoPE + bf16 hi/lo split over the fused q|k buffer (width 2560).
// ---------------------------------------------------------------------------
#define PAIRS_PER_ROW 1280   // 1024 q + 256 k

__global__ void rope_split_kernel(const float* __restrict__ qk,
                                  const float* __restrict__ cs,
                                  const float* __restrict__ sn)
{
    int idx = blockIdx.x * blockDim.x + threadIdx.x;
    if (idx >= B * S * PAIRS_PER_ROW) return;
    int row = idx / PAIRS_PER_ROW;
    int pid = idx - row * PAIRS_PER_ROW;
    int s = row & (S - 1);

    if (pid < 1024) {                 // q
        int h = pid >> 5, d = pid & 31;
        const float* base = qk + (size_t)row * 2560 + h * 64;
        float v1 = base[d], v2 = base[d + 32];
        float c = cs[s * 32 + d], si = sn[s * 32 + d];
        float r1 = v1 * c - v2 * si;
        float r2 = v2 * c + v1 * si;
        __nv_bfloat16 h1, l1, h2, l2;
        splitf(r1, h1, l1); splitf(r2, h2, l2);
        size_t o = ((size_t)row * HQ + h) * 64 + d;
        g_qhi[o] = h1; g_qlo[o] = l1;
        g_qhi[o + 32] = h2; g_qlo[o + 32] = l2;
    } else {                          // k
        int kp = pid - 1024;
        int h = kp >> 5, d = kp & 31;
        const float* base = qk + (size_t)row * 2560 + 2048 + h * 64;
        float v1 = base[d], v2 = base[d + 32];
        float c = cs[s * 32 + d], si = sn[s * 32 + d];
        float r1 = v1 * c - v2 * si;
        float r2 = v2 * c + v1 * si;
        __nv_bfloat16 h1, l1, h2, l2;
        splitf(r1, h1, l1); splitf(r2, h2, l2);
        size_t o = ((size_t)row * HK + h) * 64 + d;
        g_khi[o] = h1; g_klo[o] = l1;
        g_khi[o + 32] = h2; g_klo[o + 32] = l2;
    }
}

// ---------------------------------------------------------------------------
// Tensor-core flash attention (R7-verified).
// QK: bf16 3-term. PV: p fp16 x v fp16 (1 term). fp16 out.
// ---------------------------------------------------------------------------
#define FSTRIDE 144
#define FTILE (64 * FSTRIDE)
#define FSTAGE (3 * FTILE)              // khi, klo, vh
#define QTILE (128 * FSTRIDE)
#define FLASH_SMEM (2 * FSTAGE)         // 55296

__global__ __launch_bounds__(256) void flash_mma_kernel()
{
    extern __shared__ char smem[];
    uint32_t sb = smem_u32(smem);
    int tid = threadIdx.x;
    int lane = tid & 31, wq = tid >> 5;
    int qbase = blockIdx.x * 128;
    int h = blockIdx.y, b = blockIdx.z;
    int kh = h >> 2;

    // ---- stage Q hi/lo, build fragments ----
#pragma unroll
    for (int i = 0; i < 8; i++) {
        int lin = i * 256 + tid;
        int arr = lin >> 10;
        int rem = lin & 1023;
        int row = rem >> 3;
        int seg = rem & 7;
        const __nv_bfloat16* src = arr ? g_qlo : g_qhi;
        cp16(sb + arr * QTILE + row * FSTRIDE + seg * 16,
             src + ((size_t)(b * S + qbase + row) * HQ + h) * 64 + seg * 8);
    }
    cp_commit();
    cp_wait<0>();
    __syncthreads();

    uint32_t qhi[4][4], qlo[4][4];
    {
        uint32_t qoff = (uint32_t)((wq * 16 + (lane & 15)) * FSTRIDE + (lane >> 4) * 16);
#pragma unroll
        for (int ks = 0; ks < 4; ks++) {
            ldm4(qhi[ks], sb + qoff + ks * 32);
            ldm4(qlo[ks], sb + QTILE + qoff + ks * 32);
        }
    }
    __syncthreads();

    // ---- kv staging (3 arrays: khi, klo bf16; vh fp16) ----
    const uint8_t* srcs[3];
    srcs[0] = (const uint8_t*)(g_khi + ((size_t)b * S * HK + kh) * D);
    srcs[1] = (const uint8_t*)(g_klo + ((size_t)b * S * HK + kh) * D);
    srcs[2] = (const uint8_t*)(g_vh + ((size_t)b * S * HK + kh) * D);

    auto prefetch = [&](int t) {
        uint32_t base = sb + (t & 1) * FSTAGE;
        int key0 = t * 64;
#pragma unroll
        for (int i = 0; i < 6; i++) {
            int lin = i * 256 + tid;
            int arr = lin >> 9;
            int rem = lin & 511;
            int row = rem >> 3;
            int seg = rem & 7;
            cp16(base + arr * FTILE + row * FSTRIDE + seg * 16,
                 srcs[arr] + (size_t)(key0 + row) * (HK * D * 2) + seg * 16);
        }
        cp_commit();
    };

    uint32_t boff = (uint32_t)(((lane >> 4) * 8 + (lane & 7)) * FSTRIDE
                               + ((lane >> 3) & 1) * 16);
    uint32_t voff = (uint32_t)((lane & 15) * FSTRIDE + (lane >> 4) * 16);

    float o_[8][4];
#pragma unroll
    for (int nt = 0; nt < 8; nt++)
#pragma unroll
        for (int r = 0; r < 4; r++) o_[nt][r] = 0.f;
    float m0 = -1e30f, m1 = -1e30f, l0 = 0.f, l1 = 0.f;

    prefetch(0);

    const int NT = S / 64;
    for (int t = 0; t < NT; t++) {
        if (t + 1 < NT) { prefetch(t + 1); cp_wait<1>(); }
        else           { cp_wait<0>(); }
        __syncthreads();

        uint32_t st = sb + (t & 1) * FSTAGE;
        uint32_t sKhi = st, sKlo = st + FTILE;
        uint32_t sVh = st + 2 * FTILE;

        float s[8][4];
#pragma unroll
        for (int nt = 0; nt < 8; nt++)
#pragma unroll
            for (int r = 0; r < 4; r++) s[nt][r] = 0.f;

#pragma unroll
        for (int ks = 0; ks < 4; ks++) {
            uint32_t kb = ks * 32;
            uint32_t bh[16], bl[16];
#pragma unroll
            for (int j = 0; j < 4; j++)
                ldm4(bh + 4*j, sKhi + boff + j * 16 * FSTRIDE + kb);
#pragma unroll
            for (int j = 0; j < 4; j++)
                ldm4(bl + 4*j, sKlo + boff + j * 16 * FSTRIDE + kb);
#pragma unroll
            for (int nt = 0; nt < 8; nt++) {
                mma_bf16(s[nt], qhi[ks], bh + 2*nt);
                mma_bf16(s[nt], qhi[ks], bl + 2*nt);
                mma_bf16(s[nt], qlo[ks], bh + 2*nt);
            }
        }

        float tmax0 = -1e30f, tmax1 = -1e30f;
#pragma unroll
        for (int nt = 0; nt < 8; nt++) {
            tmax0 = fmaxf(tmax0, fmaxf(s[nt][0], s[nt][1]));
            tmax1 = fmaxf(tmax1, fmaxf(s[nt][2], s[nt][3]));
        }
        tmax0 = fmaxf(tmax0, __shfl_xor_sync(0xffffffffu, tmax0, 1));
        tmax0 = fmaxf(tmax0, __shfl_xor_sync(0xffffffffu, tmax0, 2));
        tmax1 = fmaxf(tmax1, __shfl_xor_sync(0xffffffffu, tmax1, 1));
        tmax1 = fmaxf(tmax1, __shfl_xor_sync(0xffffffffu, tmax1, 2));
        float nm0 = fmaxf(m0, tmax0), nm1 = fmaxf(m1, tmax1);
        float a0 = __expf(m0 - nm0), a1 = __expf(m1 - nm1);
        m0 = nm0; m1 = nm1;
        float ps0 = 0.f, ps1 = 0.f;
#pragma unroll
        for (int nt = 0; nt < 8; nt++) {
            s[nt][0] = __expf(s[nt][0] - m0);
            s[nt][1] = __expf(s[nt][1] - m0);
            s[nt][2] = __expf(s[nt][2] - m1);
            s[nt][3] = __expf(s[nt][3] - m1);
            ps0 += s[nt][0] + s[nt][1];
            ps1 += s[nt][2] + s[nt][3];
        }
        l0 = l0 * a0 + ps0;
        l1 = l1 * a1 + ps1;
#pragma unroll
        for (int nt = 0; nt < 8; nt++) {
            o_[nt][0] *= a0; o_[nt][1] *= a0;
            o_[nt][2] *= a1; o_[nt][3] *= a1;
        }

        // ---- PV: p fp16 x v fp16, single term ----
#pragma unroll
        for (int ks = 0; ks < 4; ks++) {
            uint32_t ph[4];
            ph[0] = packh(s[2*ks][0],   s[2*ks][1]);
            ph[1] = packh(s[2*ks][2],   s[2*ks][3]);
            ph[2] = packh(s[2*ks+1][0], s[2*ks+1][1]);
            ph[3] = packh(s[2*ks+1][2], s[2*ks+1][3]);
            uint32_t rbase = ks * 16 * FSTRIDE;
#pragma unroll
            for (int n2 = 0; n2 < 4; n2++) {
                uint32_t vh[4];
                ldm4t(vh, sVh + voff + rbase + n2 * 32);
                mma_f16(o_[2*n2],     ph, vh + 0);
                mma_f16(o_[2*n2 + 1], ph, vh + 2);
            }
        }
        __syncthreads();
    }

    // ---- finalize: write single fp16 ----
    l0 += __shfl_xor_sync(0xffffffffu, l0, 1);
    l0 += __shfl_xor_sync(0xffffffffu, l0, 2);
    l1 += __shfl_xor_sync(0xffffffffu, l1, 1);
    l1 += __shfl_xor_sync(0xffffffffu, l1, 2);
    float inv0 = 1.f / l0, inv1 = 1.f / l1;

    int r = qbase + wq * 16 + (lane >> 2);
    int c = (lane & 3) * 2;
    size_t ob0 = ((size_t)(b * S + r) * HQ + h) * D;
    size_t ob1 = ((size_t)(b * S + r + 8) * HQ + h) * D;
#pragma unroll
    for (int nt = 0; nt < 8; nt++) {
        *(uint32_t*)(g_of + ob0 + nt * 8 + c) =
            packh(o_[nt][0] * inv0, o_[nt][1] * inv0);
        *(uint32_t*)(g_of + ob1 + nt * 8 + c) =
            packh(o_[nt][2] * inv1, o_[nt][3] * inv1);
    }
}

// ---------------------------------------------------------------------------
// Launch
// ---------------------------------------------------------------------------
extern "C" void kernel_launch(void* const* d_in, const int* in_sizes, int n_in,
                              void* d_out, int out_size)
{
    const float* x    = (const float*)d_in[0];
    const float* rcos = (const float*)d_in[1];
    const float* rsin = (const float*)d_in[2];
    const float* Wq   = (const float*)d_in[4];
    const float* Wk   = (const float*)d_in[5];
    const float* Wv   = (const float*)d_in[6];
    const float* Wo   = (const float*)d_in[7];
    float* out = (float*)d_out;

    float* qkp;
    cudaGetSymbolAddress((void**)&qkp, g_qk);
    __nv_bfloat16 *xhi, *xlo, *wqkhi, *wqklo;
    __half *xh, *wvh, *wohf, *vhp, *ofp;
    cudaGetSymbolAddress((void**)&xhi, g_xhi);
    cudaGetSymbolAddress((void**)&xlo, g_xlo);
    cudaGetSymbolAddress((void**)&xh, g_xh);
    cudaGetSymbolAddress((void**)&wqkhi, g_wqkhi);
    cudaGetSymbolAddress((void**)&wqklo, g_wqklo);
    cudaGetSymbolAddress((void**)&wvh, g_wvh);
    cudaGetSymbolAddress((void**)&wohf, g_wohf);
    cudaGetSymbolAddress((void**)&vhp, g_vh);
    cudaGetSymbolAddress((void**)&ofp, g_of);

    cudaFuncSetAttribute(mma_gemm_kernel,
                         cudaFuncAttributeMaxDynamicSharedMemorySize, GEMM_SMEM);
    cudaFuncSetAttribute(mma_gemm1_kernel<false>,
                         cudaFuncAttributeMaxDynamicSharedMemorySize, GEMM1_SMEM);
    cudaFuncSetAttribute(mma_gemm1_kernel<true>,
                         cudaFuncAttributeMaxDynamicSharedMemorySize, GEMM1_SMEM);
    cudaFuncSetAttribute(flash_mma_kernel,
                         cudaFuncAttributeMaxDynamicSharedMemorySize, FLASH_SMEM);

    const int M = B * S;  // 4096

    // 0) split x -> bf16 hi/lo + fp16
    {
        int n4 = M * E / 4;
        split3_kernel<<<(n4 + 255) / 256, 256>>>(x, xhi, xlo, xh, n4);
    }
    // 1-2) transpose+split Wq/Wk (bf16) into concatenated [2560, 2048]
    transpose_split_kernel<<<dim3((HQ*D)/32, E/32), dim3(32, 8)>>>(
        Wq, wqkhi, wqklo, E, HQ*D);
    transpose_split_kernel<<<dim3((HK*D)/32, E/32), dim3(32, 8)>>>(
        Wk, wqkhi + (size_t)2048 * E, wqklo + (size_t)2048 * E, E, HK*D);
    // 3) transpose Wv (fp16), 4) transpose Wo (fp16)
    transpose_h_kernel<<<dim3((HK*D)/32, E/32), dim3(32, 8)>>>(Wv, wvh, E, HK*D);
    transpose_h_kernel<<<dim3(E/32, (HQ*D)/32), dim3(32, 8)>>>(Wo, wohf, HQ*D, E);

    // 5) fused Q|K projection (bf16 3-term): [4096, 2560]
    mma_gemm_kernel<<<dim3(2560/128, M/128), 256, GEMM_SMEM>>>(
        M, 2560, E, xhi, xlo, wqkhi, wqklo, qkp);

    // 6) V projection (fp16 single term), writes g_vh directly
    mma_gemm1_kernel<true><<<dim3(512/128, M/128), 256, GEMM1_SMEM>>>(
        M, 512, E, xh, wvh, (void*)vhp);

    // 7) fused RoPE + split (q,k only)
    {
        int tot = B * S * PAIRS_PER_ROW;
        rope_split_kernel<<<(tot + 255) / 256, 256>>>(qkp, rcos, rsin);
    }

    // 8) tensor-core flash attention
    flash_mma_kernel<<<dim3(S / 128, HQ, B), 256, FLASH_SMEM>>>();

    // 9) O-projection (fp16, single term)
    mma_gemm1_kernel<false><<<dim3(E/128, M/128), 256, GEMM1_SMEM>>>(
        M, E, HQ*D, ofp, wohf, (void*)out);
}

// round 11
// speedup vs baseline: 1.6440x; 1.1165x over previous
#include <cuda_runtime.h>
#include <cuda_bf16.h>
#include <cuda_fp16.h>
#include <cstdint>

// Problem constants
#define B 2
#define S 2048
#define E 2048
#define HQ 32
#define HK 8
#define D 64

// ---------------------------------------------------------------------------
// Scratch (device globals)
// ---------------------------------------------------------------------------
__device__ float g_qk[(size_t)B * S * 2560];             // fused Q|K fp32

__device__ __nv_bfloat16 g_xhi[(size_t)B * S * E];
__device__ __nv_bfloat16 g_xlo[(size_t)B * S * E];
__device__ __half        g_xh[(size_t)B * S * E];        // x fp16 (for v-proj)
__device__ __nv_bfloat16 g_wqkhi[(size_t)2560 * E];      // [N=2560, K=2048]
__device__ __nv_bfloat16 g_wqklo[(size_t)2560 * E];
__device__ __half        g_wvh[(size_t)512 * E];         // Wv^T fp16
__device__ __half        g_wohf[(size_t)E * HQ * D];     // Wo^T fp16

__device__ __nv_bfloat16 g_qhi[(size_t)B * S * HQ * D]; // post-RoPE bf16
__device__ __nv_bfloat16 g_qlo[(size_t)B * S * HQ * D];
__device__ __nv_bfloat16 g_khi[(size_t)B * S * HK * D];
__device__ __nv_bfloat16 g_klo[(size_t)B * S * HK * D];
__device__ __half        g_vh[(size_t)B * S * HK * D];  // v fp16 (from GEMM)
__device__ __half        g_of[(size_t)B * S * HQ * D];  // attention out, fp16

// ---------------------------------------------------------------------------
// PTX helpers (base-target safe)
// ---------------------------------------------------------------------------
__device__ __forceinline__ uint32_t smem_u32(const void* p) {
    uint32_t a;
    asm("{ .reg .u64 t; cvta.to.shared.u64 t, %1; cvt.u32.u64 %0, t; }"
        : "=r"(a) : "l"(p));
    return a;
}
__device__ __forceinline__ void cp16(uint32_t dst, const void* src) {
    asm volatile("cp.async.cg.shared.global [%0], [%1], 16;"
                 :: "r"(dst), "l"(src) : "memory");
}
__device__ __forceinline__ void cp_commit() {
    asm volatile("cp.async.commit_group;" ::: "memory");
}
template <int N>
__device__ __forceinline__ void cp_wait() {
    asm volatile("cp.async.wait_group %0;" :: "n"(N) : "memory");
}
__device__ __forceinline__ void ldm4(uint32_t* r, uint32_t addr) {
    asm volatile("ldmatrix.sync.aligned.m8n8.x4.shared.b16 {%0,%1,%2,%3}, [%4];"
                 : "=r"(r[0]), "=r"(r[1]), "=r"(r[2]), "=r"(r[3]) : "r"(addr));
}
__device__ __forceinline__ void ldm4t(uint32_t* r, uint32_t addr) {
    asm volatile("ldmatrix.sync.aligned.m8n8.x4.trans.shared.b16 {%0,%1,%2,%3}, [%4];"
                 : "=r"(r[0]), "=r"(r[1]), "=r"(r[2]), "=r"(r[3]) : "r"(addr));
}
__device__ __forceinline__ void mma_bf16(float* c, const uint32_t* a,
                                         const uint32_t* b) {
    asm volatile(
        "mma.sync.aligned.m16n8k16.row.col.f32.bf16.bf16.f32 "
        "{%0,%1,%2,%3}, {%4,%5,%6,%7}, {%8,%9}, {%0,%1,%2,%3};"
        : "+f"(c[0]), "+f"(c[1]), "+f"(c[2]), "+f"(c[3])
        : "r"(a[0]), "r"(a[1]), "r"(a[2]), "r"(a[3]), "r"(b[0]), "r"(b[1]));
}
__device__ __forceinline__ void mma_f16(float* c, const uint32_t* a,
                                        const uint32_t* b) {
    asm volatile(
        "mma.sync.aligned.m16n8k16.row.col.f32.f16.f16.f32 "
        "{%0,%1,%2,%3}, {%4,%5,%6,%7}, {%8,%9}, {%0,%1,%2,%3};"
        : "+f"(c[0]), "+f"(c[1]), "+f"(c[2]), "+f"(c[3])
        : "r"(a[0]), "r"(a[1]), "r"(a[2]), "r"(a[3]), "r"(b[0]), "r"(b[1]));
}
__device__ __forceinline__ uint32_t packbf(__nv_bfloat16 a, __nv_bfloat16 b) {
    __nv_bfloat162 t = __halves2bfloat162(a, b);
    return *(uint32_t*)&t;
}
__device__ __forceinline__ uint32_t packh(float x, float y) {
    __half2 t = __floats2half2_rn(x, y);
    return *(uint32_t*)&t;
}
__device__ __forceinline__ void split2(float x, float y,
                                       uint32_t& hi, uint32_t& lo) {
    __nv_bfloat16 hx = __float2bfloat16(x), hy = __float2bfloat16(y);
    __nv_bfloat16 lx = __float2bfloat16(x - __bfloat162float(hx));
    __nv_bfloat16 ly = __float2bfloat16(y - __bfloat162float(hy));
    hi = packbf(hx, hy);
    lo = packbf(lx, ly);
}
__device__ __forceinline__ void splitf(float x, __nv_bfloat16& h, __nv_bfloat16& l) {
    h = __float2bfloat16(x);
    l = __float2bfloat16(x - __bfloat162float(h));
}

// ---------------------------------------------------------------------------
// Split fp32 -> bf16 hi/lo + fp16 single
// ---------------------------------------------------------------------------
__global__ void split3_kernel(const float* __restrict__ src,
                              __nv_bfloat16* __restrict__ hi,
                              __nv_bfloat16* __restrict__ lo,
                              __half* __restrict__ hf, int n4)
{
    int i = blockIdx.x * blockDim.x + threadIdx.x;
    if (i >= n4) return;
    float4 v = ((const float4*)src)[i];
    uint32_t h0, l0, h1, l1;
    split2(v.x, v.y, h0, l0);
    split2(v.z, v.w, h1, l1);
    ((uint32_t*)hi)[2*i]   = h0;
    ((uint32_t*)hi)[2*i+1] = h1;
    ((uint32_t*)lo)[2*i]   = l0;
    ((uint32_t*)lo)[2*i+1] = l1;
    ((uint32_t*)hf)[2*i]   = packh(v.x, v.y);
    ((uint32_t*)hf)[2*i+1] = packh(v.z, v.w);
}

// ---------------------------------------------------------------------------
// Transpose W[K,N] -> Wt[N,K], bf16 hi/lo
// ---------------------------------------------------------------------------
__global__ __launch_bounds__(256) void transpose_split_kernel(
    const float* __restrict__ W,
    __nv_bfloat16* __restrict__ hiT,
    __nv_bfloat16* __restrict__ loT, int K, int N)
{
    __shared__ float t[32][33];
    int n0 = blockIdx.x * 32, k0 = blockIdx.y * 32;
    int tx = threadIdx.x, ty = threadIdx.y;
#pragma unroll
    for (int r = 0; r < 4; r++)
        t[ty + r*8][tx] = W[(size_t)(k0 + ty + r*8) * N + n0 + tx];
    __syncthreads();
#pragma unroll
    for (int r = 0; r < 4; r++) {
        int n = n0 + ty + r*8;
        float v = t[tx][ty + r*8];
        __nv_bfloat16 h = __float2bfloat16(v);
        hiT[(size_t)n * K + k0 + tx] = h;
        loT[(size_t)n * K + k0 + tx] = __float2bfloat16(v - __bfloat162float(h));
    }
}

// Transpose W[K,N] -> Wt[N,K], single fp16
__global__ __launch_bounds__(256) void transpose_h_kernel(
    const float* __restrict__ W,
    __half* __restrict__ hT, int K, int N)
{
    __shared__ float t[32][33];
    int n0 = blockIdx.x * 32, k0 = blockIdx.y * 32;
    int tx = threadIdx.x, ty = threadIdx.y;
#pragma unroll
    for (int r = 0; r < 4; r++)
        t[ty + r*8][tx] = W[(size_t)(k0 + ty + r*8) * N + n0 + tx];
    __syncthreads();
#pragma unroll
    for (int r = 0; r < 4; r++) {
        int n = n0 + ty + r*8;
        hT[(size_t)n * K + k0 + tx] = __float2half_rn(t[tx][ty + r*8]);
    }
}

// ---------------------------------------------------------------------------
// mma.sync bf16 3-term GEMM (verified) — now 2 CTAs/SM
// ---------------------------------------------------------------------------
#define TSTRIDE 80
#define TILE_BYTES (128 * TSTRIDE)
#define STAGE_BYTES (4 * TILE_BYTES)
#define GEMM_SMEM (2 * STAGE_BYTES)

__device__ __forceinline__ void load_stage(
    uint32_t base, int tid,
    const __nv_bfloat16* Ah, const __nv_bfloat16* Al,
    const __nv_bfloat16* Bh, const __nv_bfloat16* Bl,
    int K, int k0)
{
    int ch = tid & 3;
    int rhalf = tid >> 2;
#pragma unroll
    for (int i = 0; i < 8; i++) {
        int tile = i >> 1;
        int row = (i & 1) * 64 + rhalf;
        uint32_t dst = base + tile * TILE_BYTES + row * TSTRIDE + ch * 16;
        const __nv_bfloat16* src =
            (tile == 0) ? Ah : (tile == 1) ? Al : (tile == 2) ? Bh : Bl;
        cp16(dst, src + (size_t)row * K + k0 + ch * 8);
    }
}

__global__ __launch_bounds__(256, 2) void mma_gemm_kernel(
    int M, int N, int K,
    const __nv_bfloat16* __restrict__ Ahi, const __nv_bfloat16* __restrict__ Alo,
    const __nv_bfloat16* __restrict__ Bhi, const __nv_bfloat16* __restrict__ Blo,
    float* __restrict__ C)
{
    extern __shared__ char smem[];
    uint32_t sb = smem_u32(smem);
    int tid = threadIdx.x;
    int lane = tid & 31, wid = tid >> 5;
    int wm = wid & 1, wn = wid >> 1;
    int bm = blockIdx.y * 128, bn = blockIdx.x * 128;

    const __nv_bfloat16* Ah = Ahi + (size_t)bm * K;
    const __nv_bfloat16* Al = Alo + (size_t)bm * K;
    const __nv_bfloat16* Bh = Bhi + (size_t)bn * K;
    const __nv_bfloat16* Bl = Blo + (size_t)bn * K;

    float acc[4][4][4];
#pragma unroll
    for (int i = 0; i < 4; i++)
#pragma unroll
        for (int j = 0; j < 4; j++)
#pragma unroll
            for (int r = 0; r < 4; r++) acc[i][j][r] = 0.f;

    uint32_t aoff = (uint32_t)((wm * 64 + (lane & 15)) * TSTRIDE + (lane >> 4) * 16);
    uint32_t boff = (uint32_t)((wn * 32 + ((lane >> 4) * 8) + (lane & 7)) * TSTRIDE
                               + ((lane >> 3) & 1) * 16);

    const int nch = K >> 5;
    load_stage(sb, tid, Ah, Al, Bh, Bl, K, 0);
    cp_commit();

    for (int ch = 0; ch < nch; ch++) {
        if (ch + 1 < nch) {
            load_stage(sb + ((ch + 1) & 1) * STAGE_BYTES, tid,
                       Ah, Al, Bh, Bl, K, (ch + 1) << 5);
            cp_commit();
            cp_wait<1>();
        } else {
            cp_wait<0>();
        }
        __syncthreads();

        uint32_t st = sb + (ch & 1) * STAGE_BYTES;
        uint32_t sAhi = st;
        uint32_t sAlo = st + TILE_BYTES;
        uint32_t sBhi = st + 2 * TILE_BYTES;
        uint32_t sBlo = st + 3 * TILE_BYTES;

#pragma unroll
        for (int ks = 0; ks < 2; ks++) {
            uint32_t kb = ks * 32;
            uint32_t bh[8], bl[8], a[16];
            ldm4(bh + 0, sBhi + boff + kb);
            ldm4(bh + 4, sBhi + boff + 16 * TSTRIDE + kb);
            ldm4(bl + 0, sBlo + boff + kb);
            ldm4(bl + 4, sBlo + boff + 16 * TSTRIDE + kb);
#pragma unroll
            for (int mt = 0; mt < 4; mt++)
                ldm4(a + 4 * mt, sAhi + aoff + mt * 16 * TSTRIDE + kb);
#pragma unroll
            for (int mt = 0; mt < 4; mt++)
#pragma unroll
                for (int nt = 0; nt < 4; nt++)
                    mma_bf16(acc[mt][nt], a + 4 * mt, bh + 2 * nt);
#pragma unroll
            for (int mt = 0; mt < 4; mt++)
#pragma unroll
                for (int nt = 0; nt < 4; nt++)
                    mma_bf16(acc[mt][nt], a + 4 * mt, bl + 2 * nt);
#pragma unroll
            for (int mt = 0; mt < 4; mt++)
                ldm4(a + 4 * mt, sAlo + aoff + mt * 16 * TSTRIDE + kb);
#pragma unroll
            for (int mt = 0; mt < 4; mt++)
#pragma unroll
                for (int nt = 0; nt < 4; nt++)
                    mma_bf16(acc[mt][nt], a + 4 * mt, bh + 2 * nt);
        }
        __syncthreads();
    }

    int r0 = bm + wm * 64 + (lane >> 2);
    int c0 = bn + wn * 32 + (lane & 3) * 2;
#pragma unroll
    for (int mt = 0; mt < 4; mt++) {
#pragma unroll
        for (int nt = 0; nt < 4; nt++) {
            int row = r0 + mt * 16;
            int col = c0 + nt * 8;
            *(float2*)&C[(size_t)row * N + col] =
                make_float2(acc[mt][nt][0], acc[mt][nt][1]);
            *(float2*)&C[(size_t)(row + 8) * N + col] =
                make_float2(acc[mt][nt][2], acc[mt][nt][3]);
        }
    }
}

// ---------------------------------------------------------------------------
// fp16 single-term GEMM — 2 CTAs/SM
// ---------------------------------------------------------------------------
#define STAGE1_BYTES (2 * TILE_BYTES)
#define GEMM1_SMEM (2 * STAGE1_BYTES)

__device__ __forceinline__ void load_stage1(
    uint32_t base, int tid,
    const __half* A, const __half* Bh, int K, int k0)
{
    int ch = tid & 3;
    int rhalf = tid >> 2;
#pragma unroll
    for (int i = 0; i < 4; i++) {
        int tile = i >> 1;
        int row = (i & 1) * 64 + rhalf;
        uint32_t dst = base + tile * TILE_BYTES + row * TSTRIDE + ch * 16;
        const __half* src = (tile == 0) ? A : Bh;
        cp16(dst, src + (size_t)row * K + k0 + ch * 8);
    }
}

template <bool HALF_OUT>
__global__ __launch_bounds__(256, 2) void mma_gemm1_kernel(
    int M, int N, int K,
    const __half* __restrict__ A,
    const __half* __restrict__ Bhi,
    void* __restrict__ Cout)
{
    extern __shared__ char smem[];
    uint32_t sb = smem_u32(smem);
    int tid = threadIdx.x;
    int lane = tid & 31, wid = tid >> 5;
    int wm = wid & 1, wn = wid >> 1;
    int bm = blockIdx.y * 128, bn = blockIdx.x * 128;

    const __half* Ap = A + (size_t)bm * K;
    const __half* Bh = Bhi + (size_t)bn * K;

    float acc[4][4][4];
#pragma unroll
    for (int i = 0; i < 4; i++)
#pragma unroll
        for (int j = 0; j < 4; j++)
#pragma unroll
            for (int r = 0; r < 4; r++) acc[i][j][r] = 0.f;

    uint32_t aoff = (uint32_t)((wm * 64 + (lane & 15)) * TSTRIDE + (lane >> 4) * 16);
    uint32_t boff = (uint32_t)((wn * 32 + ((lane >> 4) * 8) + (lane & 7)) * TSTRIDE
                               + ((lane >> 3) & 1) * 16);

    const int nch = K >> 5;
    load_stage1(sb, tid, Ap, Bh, K, 0);
    cp_commit();

    for (int ch = 0; ch < nch; ch++) {
        if (ch + 1 < nch) {
            load_stage1(sb + ((ch + 1) & 1) * STAGE1_BYTES, tid,
                        Ap, Bh, K, (ch + 1) << 5);
            cp_commit();
            cp_wait<1>();
        } else {
            cp_wait<0>();
        }
        __syncthreads();

        uint32_t st = sb + (ch & 1) * STAGE1_BYTES;
        uint32_t sA = st;
        uint32_t sB = st + TILE_BYTES;

#pragma unroll
        for (int ks = 0; ks < 2; ks++) {
            uint32_t kb = ks * 32;
            uint32_t bh[8], a[16];
            ldm4(bh + 0, sB + boff + kb);
            ldm4(bh + 4, sB + boff + 16 * TSTRIDE + kb);
#pragma unroll
            for (int mt = 0; mt < 4; mt++)
                ldm4(a + 4 * mt, sA + aoff + mt * 16 * TSTRIDE + kb);
#pragma unroll
            for (int mt = 0; mt < 4; mt++)
#pragma unroll
                for (int nt = 0; nt < 4; nt++)
                    mma_f16(acc[mt][nt], a + 4 * mt, bh + 2 * nt);
        }
        __syncthreads();
    }

    int r0 = bm + wm * 64 + (lane >> 2);
    int c0 = bn + wn * 32 + (lane & 3) * 2;
#pragma unroll
    for (int mt = 0; mt < 4; mt++) {
#pragma unroll
        for (int nt = 0; nt < 4; nt++) {
            int row = r0 + mt * 16;
            int col = c0 + nt * 8;
            if (HALF_OUT) {
                __half* C = (__half*)Cout;
                *(uint32_t*)&C[(size_t)row * N + col] =
                    packh(acc[mt][nt][0], acc[mt][nt][1]);
                *(uint32_t*)&C[(size_t)(row + 8) * N + col] =
                    packh(acc[mt][nt][2], acc[mt][nt][3]);
            } else {
                float* C = (float*)Cout;
                *(float2*)&C[(size_t)row * N + col] =
                    make_float2(acc[mt][nt][0], acc[mt][nt][1]);
                *(float2*)&C[(size_t)(row + 8) * N + col] =
                    make_float2(acc[mt][nt][2], acc[mt][nt][3]);
            }
        }
    }
}

// ---------------------------------------------------------------------------
// Fused RoPE + bf16 hi/lo split over the fused q|k buffer (width 2560).
// ---------------------------------------------------------------------------
#define PAIRS_PER_ROW 1280   // 1024 q + 256 k

__global__ void rope_split_kernel(const float* __restrict__ qk,
                                  const float* __restrict__ cs,
                                  const float* __restrict__ sn)
{
    int idx = blockIdx.x * blockDim.x + threadIdx.x;
    if (idx >= B * S * PAIRS_PER_ROW) return;
    int row = idx / PAIRS_PER_ROW;
    int pid = idx - row * PAIRS_PER_ROW;
    int s = row & (S - 1);

    if (pid < 1024) {                 // q
        int h = pid >> 5, d = pid & 31;
        const float* base = qk + (size_t)row * 2560 + h * 64;
        float v1 = base[d], v2 = base[d + 32];
        float c = cs[s * 32 + d], si = sn[s * 32 + d];
        float r1 = v1 * c - v2 * si;
        float r2 = v2 * c + v1 * si;
        __nv_bfloat16 h1, l1, h2, l2;
        splitf(r1, h1, l1); splitf(r2, h2, l2);
        size_t o = ((size_t)row * HQ + h) * 64 + d;
        g_qhi[o] = h1; g_qlo[o] = l1;
        g_qhi[o + 32] = h2; g_qlo[o + 32] = l2;
    } else {                          // k
        int kp = pid - 1024;
        int h = kp >> 5, d = kp & 31;
        const float* base = qk + (size_t)row * 2560 + 2048 + h * 64;
        float v1 = base[d], v2 = base[d + 32];
        float c = cs[s * 32 + d], si = sn[s * 32 + d];
        float r1 = v1 * c - v2 * si;
        float r2 = v2 * c + v1 * si;
        __nv_bfloat16 h1, l1, h2, l2;
        splitf(r1, h1, l1); splitf(r2, h2, l2);
        size_t o = ((size_t)row * HK + h) * 64 + d;
        g_khi[o] = h1; g_klo[o] = l1;
        g_khi[o + 32] = h2; g_klo[o + 32] = l2;
    }
}

// ---------------------------------------------------------------------------
// Tensor-core flash attention — target 2 CTAs/SM (reduced b-frag live range).
// QK: bf16 3-term. PV: p fp16 x v fp16 (1 term). fp16 out.
// ---------------------------------------------------------------------------
#define FSTRIDE 144
#define FTILE (64 * FSTRIDE)
#define FSTAGE (3 * FTILE)              // khi, klo, vh
#define QTILE (128 * FSTRIDE)
#define FLASH_SMEM (2 * FSTAGE)         // 55296

__global__ __launch_bounds__(256, 2) void flash_mma_kernel()
{
    extern __shared__ char smem[];
    uint32_t sb = smem_u32(smem);
    int tid = threadIdx.x;
    int lane = tid & 31, wq = tid >> 5;
    int qbase = blockIdx.x * 128;
    int h = blockIdx.y, b = blockIdx.z;
    int kh = h >> 2;

    // ---- stage Q hi/lo, build fragments ----
#pragma unroll
    for (int i = 0; i < 8; i++) {
        int lin = i * 256 + tid;
        int arr = lin >> 10;
        int rem = lin & 1023;
        int row = rem >> 3;
        int seg = rem & 7;
        const __nv_bfloat16* src = arr ? g_qlo : g_qhi;
        cp16(sb + arr * QTILE + row * FSTRIDE + seg * 16,
             src + ((size_t)(b * S + qbase + row) * HQ + h) * 64 + seg * 8);
    }
    cp_commit();
    cp_wait<0>();
    __syncthreads();

    uint32_t qhi[4][4], qlo[4][4];
    {
        uint32_t qoff = (uint32_t)((wq * 16 + (lane & 15)) * FSTRIDE + (lane >> 4) * 16);
#pragma unroll
        for (int ks = 0; ks < 4; ks++) {
            ldm4(qhi[ks], sb + qoff + ks * 32);
            ldm4(qlo[ks], sb + QTILE + qoff + ks * 32);
        }
    }
    __syncthreads();

    // ---- kv staging (3 arrays: khi, klo bf16; vh fp16) ----
    const uint8_t* srcs[3];
    srcs[0] = (const uint8_t*)(g_khi + ((size_t)b * S * HK + kh) * D);
    srcs[1] = (const uint8_t*)(g_klo + ((size_t)b * S * HK + kh) * D);
    srcs[2] = (const uint8_t*)(g_vh + ((size_t)b * S * HK + kh) * D);

    auto prefetch = [&](int t) {
        uint32_t base = sb + (t & 1) * FSTAGE;
        int key0 = t * 64;
#pragma unroll
        for (int i = 0; i < 6; i++) {
            int lin = i * 256 + tid;
            int arr = lin >> 9;
            int rem = lin & 511;
            int row = rem >> 3;
            int seg = rem & 7;
            cp16(base + arr * FTILE + row * FSTRIDE + seg * 16,
                 srcs[arr] + (size_t)(key0 + row) * (HK * D * 2) + seg * 16);
        }
        cp_commit();
    };

    uint32_t boff = (uint32_t)(((lane >> 4) * 8 + (lane & 7)) * FSTRIDE
                               + ((lane >> 3) & 1) * 16);
    uint32_t voff = (uint32_t)((lane & 15) * FSTRIDE + (lane >> 4) * 16);

    float o_[8][4];
#pragma unroll
    for (int nt = 0; nt < 8; nt++)
#pragma unroll
        for (int r = 0; r < 4; r++) o_[nt][r] = 0.f;
    float m0 = -1e30f, m1 = -1e30f, l0 = 0.f, l1 = 0.f;

    prefetch(0);

    const int NT = S / 64;
    for (int t = 0; t < NT; t++) {
        if (t + 1 < NT) { prefetch(t + 1); cp_wait<1>(); }
        else           { cp_wait<0>(); }
        __syncthreads();

        uint32_t st = sb + (t & 1) * FSTAGE;
        uint32_t sKhi = st, sKlo = st + FTILE;
        uint32_t sVh = st + 2 * FTILE;

        float s[8][4];
#pragma unroll
        for (int nt = 0; nt < 8; nt++)
#pragma unroll
            for (int r = 0; r < 4; r++) s[nt][r] = 0.f;

        // QK, processed in two 4-nt halves to halve b-frag live range
#pragma unroll
        for (int ks = 0; ks < 4; ks++) {
            uint32_t kb = ks * 32;
#pragma unroll
            for (int hf = 0; hf < 2; hf++) {
                uint32_t rb = hf * 32 * FSTRIDE;
                uint32_t bh[8], bl[8];
                ldm4(bh + 0, sKhi + boff + rb + kb);
                ldm4(bh + 4, sKhi + boff + rb + 16 * FSTRIDE + kb);
                ldm4(bl + 0, sKlo + boff + rb + kb);
                ldm4(bl + 4, sKlo + boff + rb + 16 * FSTRIDE + kb);
#pragma unroll
                for (int j = 0; j < 4; j++) {
                    int nt = hf * 4 + j;
                    mma_bf16(s[nt], qhi[ks], bh + 2*j);
                    mma_bf16(s[nt], qhi[ks], bl + 2*j);
                    mma_bf16(s[nt], qlo[ks], bh + 2*j);
                }
            }
        }

        float tmax0 = -1e30f, tmax1 = -1e30f;
#pragma unroll
        for (int nt = 0; nt < 8; nt++) {
            tmax0 = fmaxf(tmax0, fmaxf(s[nt][0], s[nt][1]));
            tmax1 = fmaxf(tmax1, fmaxf(s[nt][2], s[nt][3]));
        }
        tmax0 = fmaxf(tmax0, __shfl_xor_sync(0xffffffffu, tmax0, 1));
        tmax0 = fmaxf(tmax0, __shfl_xor_sync(0xffffffffu, tmax0, 2));
        tmax1 = fmaxf(tmax1, __shfl_xor_sync(0xffffffffu, tmax1, 1));
        tmax1 = fmaxf(tmax1, __shfl_xor_sync(0xffffffffu, tmax1, 2));
        float nm0 = fmaxf(m0, tmax0), nm1 = fmaxf(m1, tmax1);
        float a0 = __expf(m0 - nm0), a1 = __expf(m1 - nm1);
        m0 = nm0; m1 = nm1;
        float ps0 = 0.f, ps1 = 0.f;
#pragma unroll
        for (int nt = 0; nt < 8; nt++) {
            s[nt][0] = __expf(s[nt][0] - m0);
            s[nt][1] = __expf(s[nt][1] - m0);
            s[nt][2] = __expf(s[nt][2] - m1);
            s[nt][3] = __expf(s[nt][3] - m1);
            ps0 += s[nt][0] + s[nt][1];
            ps1 += s[nt][2] + s[nt][3];
        }
        l0 = l0 * a0 + ps0;
        l1 = l1 * a1 + ps1;
#pragma unroll
        for (int nt = 0; nt < 8; nt++) {
            o_[nt][0] *= a0; o_[nt][1] *= a0;
            o_[nt][2] *= a1; o_[nt][3] *= a1;
        }

        // ---- PV: p fp16 x v fp16, single term ----
#pragma unroll
        for (int ks = 0; ks < 4; ks++) {
            uint32_t ph[4];
            ph[0] = packh(s[2*ks][0],   s[2*ks][1]);
            ph[1] = packh(s[2*ks][2],   s[2*ks][3]);
            ph[2] = packh(s[2*ks+1][0], s[2*ks+1][1]);
            ph[3] = packh(s[2*ks+1][2], s[2*ks+1][3]);
            uint32_t rbase = ks * 16 * FSTRIDE;
#pragma unroll
            for (int n2 = 0; n2 < 4; n2++) {
                uint32_t vh[4];
                ldm4t(vh, sVh + voff + rbase + n2 * 32);
                mma_f16(o_[2*n2],     ph, vh + 0);
                mma_f16(o_[2*n2 + 1], ph, vh + 2);
            }
        }
        __syncthreads();
    }

    // ---- finalize: write single fp16 ----
    l0 += __shfl_xor_sync(0xffffffffu, l0, 1);
    l0 += __shfl_xor_sync(0xffffffffu, l0, 2);
    l1 += __shfl_xor_sync(0xffffffffu, l1, 1);
    l1 += __shfl_xor_sync(0xffffffffu, l1, 2);
    float inv0 = 1.f / l0, inv1 = 1.f / l1;

    int r = qbase + wq * 16 + (lane >> 2);
    int c = (lane & 3) * 2;
    size_t ob0 = ((size_t)(b * S + r) * HQ + h) * D;
    size_t ob1 = ((size_t)(b * S + r + 8) * HQ + h) * D;
#pragma unroll
    for (int nt = 0; nt < 8; nt++) {
        *(uint32_t*)(g_of + ob0 + nt * 8 + c) =
            packh(o_[nt][0] * inv0, o_[nt][1] * inv0);
        *(uint32_t*)(g_of + ob1 + nt * 8 + c) =
            packh(o_[nt][2] * inv1, o_[nt][3] * inv1);
    }
}

// ---------------------------------------------------------------------------
// Launch
// ---------------------------------------------------------------------------
extern "C" void kernel_launch(void* const* d_in, const int* in_sizes, int n_in,
                              void* d_out, int out_size)
{
    const float* x    = (const float*)d_in[0];
    const float* rcos = (const float*)d_in[1];
    const float* rsin = (const float*)d_in[2];
    const float* Wq   = (const float*)d_in[4];
    const float* Wk   = (const float*)d_in[5];
    const float* Wv   = (const float*)d_in[6];
    const float* Wo   = (const float*)d_in[7];
    float* out = (float*)d_out;

    float* qkp;
    cudaGetSymbolAddress((void**)&qkp, g_qk);
    __nv_bfloat16 *xhi, *xlo, *wqkhi, *wqklo;
    __half *xh, *wvh, *wohf, *vhp, *ofp;
    cudaGetSymbolAddress((void**)&xhi, g_xhi);
    cudaGetSymbolAddress((void**)&xlo, g_xlo);
    cudaGetSymbolAddress((void**)&xh, g_xh);
    cudaGetSymbolAddress((void**)&wqkhi, g_wqkhi);
    cudaGetSymbolAddress((void**)&wqklo, g_wqklo);
    cudaGetSymbolAddress((void**)&wvh, g_wvh);
    cudaGetSymbolAddress((void**)&wohf, g_wohf);
    cudaGetSymbolAddress((void**)&vhp, g_vh);
    cudaGetSymbolAddress((void**)&ofp, g_of);

    cudaFuncSetAttribute(mma_gemm_kernel,
                         cudaFuncAttributeMaxDynamicSharedMemorySize, GEMM_SMEM);
    cudaFuncSetAttribute(mma_gemm1_kernel<false>,
                         cudaFuncAttributeMaxDynamicSharedMemorySize, GEMM1_SMEM);
    cudaFuncSetAttribute(mma_gemm1_kernel<true>,
                         cudaFuncAttributeMaxDynamicSharedMemorySize, GEMM1_SMEM);
    cudaFuncSetAttribute(flash_mma_kernel,
                         cudaFuncAttributeMaxDynamicSharedMemorySize, FLASH_SMEM);

    const int M = B * S;  // 4096

    // 0) split x -> bf16 hi/lo + fp16
    {
        int n4 = M * E / 4;
        split3_kernel<<<(n4 + 255) / 256, 256>>>(x, xhi, xlo, xh, n4);
    }
    // 1-2) transpose+split Wq/Wk (bf16) into concatenated [2560, 2048]
    transpose_split_kernel<<<dim3((HQ*D)/32, E/32), dim3(32, 8)>>>(
        Wq, wqkhi, wqklo, E, HQ*D);
    transpose_split_kernel<<<dim3((HK*D)/32, E/32), dim3(32, 8)>>>(
        Wk, wqkhi + (size_t)2048 * E, wqklo + (size_t)2048 * E, E, HK*D);
    // 3) transpose Wv (fp16), 4) transpose Wo (fp16)
    transpose_h_kernel<<<dim3((HK*D)/32, E/32), dim3(32, 8)>>>(Wv, wvh, E, HK*D);
    transpose_h_kernel<<<dim3(E/32, (HQ*D)/32), dim3(32, 8)>>>(Wo, wohf, HQ*D, E);

    // 5) fused Q|K projection (bf16 3-term): [4096, 2560]
    mma_gemm_kernel<<<dim3(2560/128, M/128), 256, GEMM_SMEM>>>(
        M, 2560, E, xhi, xlo, wqkhi, wqklo, qkp);

    // 6) V projection (fp16 single term), writes g_vh directly
    mma_gemm1_kernel<true><<<dim3(512/128, M/128), 256, GEMM1_SMEM>>>(
        M, 512, E, xh, wvh, (void*)vhp);

    // 7) fused RoPE + split (q,k only)
    {
        int tot = B * S * PAIRS_PER_ROW;
        rope_split_kernel<<<(tot + 255) / 256, 256>>>(qkp, rcos, rsin);
    }

    // 8) tensor-core flash attention
    flash_mma_kernel<<<dim3(S / 128, HQ, B), 256, FLASH_SMEM>>>();

    // 9) O-projection (fp16, single term)
    mma_gemm1_kernel<false><<<dim3(E/128, M/128), 256, GEMM1_SMEM>>>(
        M, E, HQ*D, ofp, wohf, (void*)out);
}